// round 1
// baseline (speedup 1.0000x reference)
#include <cuda_runtime.h>
#include <math.h>

#define Bb 128
#define Ll 512
#define Dd 300
#define Hh 200
#define Vv 50000

// Scratch (device globals -- no allocation allowed)
__device__ float g_E[Bb * Ll * Dd];      // gathered word embeddings  (78.6 MB)
__device__ float g_P[Vv * Hh];           // emb_table @ W1_top        (40 MB)
__device__ float g_subj[Bb * Dd];
__device__ float g_obj[Bb * Dd];
__device__ float g_sup[Bb * Hh];         // subj_emb @ W1_bot + b1
__device__ float g_score[Bb * Ll];
__device__ float g_attn[Bb * Dd];

// ---------------------------------------------------------------------------
// Kernel 1: gather embeddings into g_E + masked max-pools (subj, obj)
// grid = B, block = 320 (300 active in d)
// ---------------------------------------------------------------------------
__global__ void k_gather_pool(const int* __restrict__ words,
                              const int* __restrict__ spos,
                              const int* __restrict__ opos,
                              const float* __restrict__ emb) {
    int b = blockIdx.x;
    __shared__ int sw[Ll];
    __shared__ unsigned char sm[Ll], om[Ll];
    int tid = threadIdx.x;
    for (int l = tid; l < Ll; l += blockDim.x) {
        sw[l] = words[b * Ll + l];
        sm[l] = (spos[b * Ll + l] == 0);   // keep where pos == 0
        om[l] = (opos[b * Ll + l] == 0);
    }
    __syncthreads();
    if (tid < Dd) {
        float smax = -1e12f, omax = -1e12f;
        for (int l = 0; l < Ll; l++) {
            float v = emb[(long)sw[l] * Dd + tid];
            g_E[((long)b * Ll + l) * Dd + tid] = v;
            if (sm[l]) smax = fmaxf(smax, v);
            if (om[l]) omax = fmaxf(omax, v);
        }
        g_subj[b * Dd + tid] = smax;
        g_obj[b * Dd + tid]  = omax;
    }
}

// ---------------------------------------------------------------------------
// Kernel 2: g_sup[b,h] = b1[h] + sum_d subj[b,d] * w1[(D+d), h]
// grid = B, block = 224 (200 active)
// ---------------------------------------------------------------------------
__global__ void k_supproj(const float* __restrict__ w1,
                          const float* __restrict__ b1) {
    int b = blockIdx.x;
    int tid = threadIdx.x;
    __shared__ float s[Dd];
    for (int d = tid; d < Dd; d += blockDim.x) s[d] = g_subj[b * Dd + d];
    __syncthreads();
    if (tid < Hh) {
        float acc = b1[tid];
        #pragma unroll 4
        for (int d = 0; d < Dd; d++)
            acc += s[d] * w1[(Dd + d) * Hh + tid];
        g_sup[b * Hh + tid] = acc;
    }
}

// ---------------------------------------------------------------------------
// Kernel 3: P = emb_table[V,D] @ W1_top[D,H]   (fp32 sgemm, 128x128x8 tiles,
// 8x8 per thread, 256 threads). N is padded to 128-tiles; stores are guarded.
// ---------------------------------------------------------------------------
#define BM 128
#define BN 128
#define BK 8
__global__ void __launch_bounds__(256) k_gemmP(const float* __restrict__ A,
                                               const float* __restrict__ Bw) {
    __shared__ float As[BK][BM];
    __shared__ float Bs[BK][BN + 4];
    int m0 = blockIdx.x * BM;
    int n0 = blockIdx.y * BN;
    int tid = threadIdx.x;
    int tx = tid % 16, ty = tid / 16;
    float acc[8][8];
    #pragma unroll
    for (int i = 0; i < 8; i++)
        #pragma unroll
        for (int j = 0; j < 8; j++) acc[i][j] = 0.f;

    for (int k0 = 0; k0 < Dd; k0 += BK) {
        // A tile: BM x BK -> As[k][m]
        #pragma unroll
        for (int i = tid; i < BM * BK; i += 256) {
            int r = i / BK, c = i % BK;
            int gm = m0 + r, gk = k0 + c;
            float v = 0.f;
            if (gm < Vv && gk < Dd) v = A[(long)gm * Dd + gk];
            As[c][r] = v;
        }
        // B tile: BK x BN
        #pragma unroll
        for (int i = tid; i < BK * BN; i += 256) {
            int r = i / BN, c = i % BN;
            int gk = k0 + r, gn = n0 + c;
            float v = 0.f;
            if (gk < Dd && gn < Hh) v = Bw[gk * Hh + gn];
            Bs[r][c] = v;
        }
        __syncthreads();
        #pragma unroll
        for (int kk = 0; kk < BK; kk++) {
            float a[8], bb[8];
            #pragma unroll
            for (int i = 0; i < 8; i++) a[i] = As[kk][ty * 8 + i];
            #pragma unroll
            for (int j = 0; j < 8; j++) bb[j] = Bs[kk][tx * 8 + j];
            #pragma unroll
            for (int i = 0; i < 8; i++)
                #pragma unroll
                for (int j = 0; j < 8; j++)
                    acc[i][j] += a[i] * bb[j];
        }
        __syncthreads();
    }
    #pragma unroll
    for (int i = 0; i < 8; i++) {
        int gm = m0 + ty * 8 + i;
        if (gm >= Vv) continue;
        #pragma unroll
        for (int j = 0; j < 8; j++) {
            int gn = n0 + tx * 8 + j;
            if (gn < Hh) g_P[(long)gm * Hh + gn] = acc[i][j];
        }
    }
}

// ---------------------------------------------------------------------------
// Kernel 4: scores[t] = b2 + sum_h w2[h] * tanh(P[words[t],h] + sup[b,h])
// one warp per token, 8 tokens/block
// ---------------------------------------------------------------------------
__global__ void k_scores(const int* __restrict__ words,
                         const float* __restrict__ w2,
                         const float* __restrict__ b2) {
    int t = blockIdx.x * 8 + (threadIdx.x >> 5);
    int lane = threadIdx.x & 31;
    int b = t / Ll;
    int w = words[t];
    const float* Prow = &g_P[(long)w * Hh];
    const float* Srow = &g_sup[b * Hh];
    float acc = 0.f;
    for (int h = lane; h < Hh; h += 32)
        acc += w2[h] * tanhf(Prow[h] + Srow[h]);
    #pragma unroll
    for (int o = 16; o > 0; o >>= 1) acc += __shfl_xor_sync(0xffffffffu, acc, o);
    if (lane == 0) g_score[t] = acc + b2[0];
}

// ---------------------------------------------------------------------------
// Kernel 5: per-b softmax over L + weighted sum over g_E -> g_attn[b,:]
// grid = B, block = 512
// ---------------------------------------------------------------------------
__global__ void k_attn_pool() {
    int b = blockIdx.x;
    int tid = threadIdx.x;
    __shared__ float p[Ll];
    __shared__ float red[512];
    float sc = g_score[b * Ll + tid];
    red[tid] = sc;
    __syncthreads();
    for (int s = 256; s > 0; s >>= 1) {
        if (tid < s) red[tid] = fmaxf(red[tid], red[tid + s]);
        __syncthreads();
    }
    float m = red[0];
    __syncthreads();
    float e = expf(sc - m);
    p[tid] = e;
    red[tid] = e;
    __syncthreads();
    for (int s = 256; s > 0; s >>= 1) {
        if (tid < s) red[tid] += red[tid + s];
        __syncthreads();
    }
    float inv = 1.f / red[0];
    __syncthreads();
    if (tid < Dd) {
        float acc = 0.f;
        const float* Eb = &g_E[(long)b * Ll * Dd + tid];
        #pragma unroll 4
        for (int l = 0; l < Ll; l++)
            acc += p[l] * Eb[(long)l * Dd];
        g_attn[b * Dd + tid] = acc * inv;
    }
}

// ---------------------------------------------------------------------------
// Kernel 6: feat = [attn, attn, subj, obj]; out = relu(relu(feat@mw1+mb1)@mw2+mb2)
// grid = B, block = 256 (200 active in h)
// ---------------------------------------------------------------------------
__global__ void k_mlp(const float* __restrict__ mw1, const float* __restrict__ mb1,
                      const float* __restrict__ mw2, const float* __restrict__ mb2,
                      float* __restrict__ out) {
    int b = blockIdx.x;
    int tid = threadIdx.x;
    __shared__ float feat[4 * Dd];
    __shared__ float hid[Hh];
    for (int i = tid; i < Dd; i += blockDim.x) {
        float a = g_attn[b * Dd + i];
        feat[i]           = a;           // subj_attn
        feat[Dd + i]      = a;           // obj_attn (== subj_attn, source bug)
        feat[2 * Dd + i]  = g_subj[b * Dd + i];
        feat[3 * Dd + i]  = g_obj[b * Dd + i];
    }
    __syncthreads();
    if (tid < Hh) {
        float a = mb1[tid];
        #pragma unroll 4
        for (int k = 0; k < 4 * Dd; k++)
            a += feat[k] * mw1[k * Hh + tid];
        hid[tid] = fmaxf(a, 0.f);
    }
    __syncthreads();
    if (tid < Hh) {
        float a = mb2[tid];
        #pragma unroll 4
        for (int k = 0; k < Hh; k++)
            a += hid[k] * mw2[k * Hh + tid];
        out[b * Hh + tid] = fmaxf(a, 0.f);
    }
}

// ---------------------------------------------------------------------------
extern "C" void kernel_launch(void* const* d_in, const int* in_sizes, int n_in,
                              void* d_out, int out_size) {
    const int*   words = (const int*)d_in[0];
    const int*   spos  = (const int*)d_in[1];
    const int*   opos  = (const int*)d_in[2];
    const float* emb   = (const float*)d_in[3];
    const float* w1    = (const float*)d_in[4];
    const float* b1    = (const float*)d_in[5];
    const float* w2    = (const float*)d_in[6];
    const float* b2    = (const float*)d_in[7];
    const float* mw1   = (const float*)d_in[8];
    const float* mb1   = (const float*)d_in[9];
    const float* mw2   = (const float*)d_in[10];
    const float* mb2   = (const float*)d_in[11];
    float* out = (float*)d_out;

    k_gather_pool<<<Bb, 320>>>(words, spos, opos, emb);
    k_supproj<<<Bb, 224>>>(w1, b1);
    dim3 gridP((Vv + BM - 1) / BM, (Hh + BN - 1) / BN);
    k_gemmP<<<gridP, 256>>>(emb, w1);
    k_scores<<<(Bb * Ll) / 8, 256>>>(words, w2, b2);
    k_attn_pool<<<Bb, 512>>>();
    k_mlp<<<Bb, 256>>>(mw1, mb1, mw2, mb2, out);
}

// round 2
// speedup vs baseline: 1.6566x; 1.6566x over previous
#include <cuda_runtime.h>
#include <math.h>
#include <stdint.h>

#define Bb 128
#define Ll 512
#define Dd 300
#define Hh 200
#define Vv 50000

// Scratch (device globals -- no allocation allowed)
__device__ float g_P[Vv * Hh];           // emb_table @ W1_top  (40 MB)
__device__ float g_subj[Bb * Dd];
__device__ float g_obj[Bb * Dd];
__device__ float g_sup[Bb * Hh];         // subj_emb @ W1_bot + b1
__device__ float g_score[Bb * Ll];
__device__ float g_attn[Bb * Dd];

__device__ __forceinline__ uint32_t f2tf32(float v) {
    uint32_t r;
    asm("cvt.rna.tf32.f32 %0, %1;" : "=r"(r) : "f"(v));
    return r;
}

// ---------------------------------------------------------------------------
// Kernel 1: masked max-pools over compacted kept positions + fused sup-proj
// grid = B, block = 320
// ---------------------------------------------------------------------------
__global__ void k_pools(const int* __restrict__ words,
                        const int* __restrict__ spos,
                        const int* __restrict__ opos,
                        const float* __restrict__ emb,
                        const float* __restrict__ w1,
                        const float* __restrict__ b1) {
    int b = blockIdx.x;
    int tid = threadIdx.x;
    __shared__ int sl[Ll], ol[Ll];
    __shared__ int scnt, ocnt;
    __shared__ float ssub[Dd];
    if (tid == 0) { scnt = 0; ocnt = 0; }
    __syncthreads();
    for (int l = tid; l < Ll; l += blockDim.x) {
        int w = words[b * Ll + l];
        if (spos[b * Ll + l] == 0) sl[atomicAdd(&scnt, 1)] = w;
        if (opos[b * Ll + l] == 0) ol[atomicAdd(&ocnt, 1)] = w;
    }
    __syncthreads();
    int ns = scnt, no = ocnt;
    if (tid < Dd) {
        float smax = -1e12f, omax = -1e12f;
        for (int i = 0; i < ns; i++)
            smax = fmaxf(smax, emb[(long)sl[i] * Dd + tid]);
        for (int i = 0; i < no; i++)
            omax = fmaxf(omax, emb[(long)ol[i] * Dd + tid]);
        g_subj[b * Dd + tid] = smax;
        g_obj[b * Dd + tid]  = omax;
        ssub[tid] = smax;
    }
    __syncthreads();
    // sup[b,h] = b1[h] + sum_d subj[b,d] * w1[(D+d), h]
    if (tid < Hh) {
        float acc = b1[tid];
        #pragma unroll 4
        for (int d = 0; d < Dd; d++)
            acc += ssub[d] * w1[(Dd + d) * Hh + tid];
        g_sup[b * Hh + tid] = acc;
    }
}

// ---------------------------------------------------------------------------
// Kernel 2: P = emb_table[V,300] @ W1_top[300,200]  -- tf32 tensor-core GEMM
// block tile 128(M) x 128(N), BK=32, 8 warps (2x4), warp tile 64x32,
// mma.sync.m16n8k8 tf32, fp32 accumulate. K padded 300 -> 320.
// ---------------------------------------------------------------------------
#define GBM 128
#define GBN 128
#define GBK 32
__global__ void __launch_bounds__(256) k_gemmP_tf32(const float* __restrict__ A,
                                                    const float* __restrict__ W) {
    __shared__ uint32_t As[GBM][36];    // stride 36: a-frag LDS conflict-free
    __shared__ uint32_t Bs[GBK][136];   // stride 136: b-frag LDS conflict-free

    int m0 = blockIdx.x * GBM;
    int n0 = blockIdx.y * GBN;
    int tid = threadIdx.x;
    int wid = tid >> 5;
    int lane = tid & 31;
    int g = lane >> 2, t = lane & 3;
    int warp_m = wid >> 2;               // 0..1
    int warp_n = wid & 3;                // 0..3

    float acc[4][4][4];
    #pragma unroll
    for (int i = 0; i < 4; i++)
        #pragma unroll
        for (int j = 0; j < 4; j++)
            #pragma unroll
            for (int c = 0; c < 4; c++) acc[i][j][c] = 0.f;

    for (int k0 = 0; k0 < 320; k0 += GBK) {
        // --- load A tile: 128 rows x 32 k (8 threads x float4-span per row) ---
        {
            int c4 = (tid & 7) * 4;
            #pragma unroll
            for (int p = 0; p < 4; p++) {
                int r = (tid >> 3) + p * 32;
                long gm = m0 + r;
                #pragma unroll
                for (int j = 0; j < 4; j++) {
                    int gk = k0 + c4 + j;
                    float v = (gm < Vv && gk < Dd) ? A[gm * Dd + gk] : 0.f;
                    As[r][c4 + j] = f2tf32(v);
                }
            }
        }
        // --- load B tile: 32 k x 128 n ---
        #pragma unroll
        for (int i = tid; i < GBK * GBN; i += 256) {
            int r = i >> 7, c = i & 127;
            int gk = k0 + r, gn = n0 + c;
            float v = (gk < Dd && gn < Hh) ? W[gk * Hh + gn] : 0.f;
            Bs[r][c] = f2tf32(v);
        }
        __syncthreads();

        #pragma unroll
        for (int ks = 0; ks < 4; ks++) {
            int kl = ks * 8;
            uint32_t ua[4][4], ub[4][2];
            #pragma unroll
            for (int mt = 0; mt < 4; mt++) {
                int mr = warp_m * 64 + mt * 16;
                ua[mt][0] = As[mr + g][kl + t];
                ua[mt][1] = As[mr + g + 8][kl + t];
                ua[mt][2] = As[mr + g][kl + t + 4];
                ua[mt][3] = As[mr + g + 8][kl + t + 4];
            }
            #pragma unroll
            for (int nt = 0; nt < 4; nt++) {
                int nc = warp_n * 32 + nt * 8;
                ub[nt][0] = Bs[kl + t][nc + g];
                ub[nt][1] = Bs[kl + t + 4][nc + g];
            }
            #pragma unroll
            for (int mt = 0; mt < 4; mt++)
                #pragma unroll
                for (int nt = 0; nt < 4; nt++)
                    asm volatile(
                        "mma.sync.aligned.m16n8k8.row.col.f32.tf32.tf32.f32 "
                        "{%0,%1,%2,%3}, {%4,%5,%6,%7}, {%8,%9}, {%0,%1,%2,%3};"
                        : "+f"(acc[mt][nt][0]), "+f"(acc[mt][nt][1]),
                          "+f"(acc[mt][nt][2]), "+f"(acc[mt][nt][3])
                        : "r"(ua[mt][0]), "r"(ua[mt][1]), "r"(ua[mt][2]), "r"(ua[mt][3]),
                          "r"(ub[nt][0]), "r"(ub[nt][1]));
        }
        __syncthreads();
    }

    // --- store (guards: gm < V, gn < 200; gn is always even) ---
    #pragma unroll
    for (int mt = 0; mt < 4; mt++) {
        long gm = m0 + warp_m * 64 + mt * 16 + g;
        #pragma unroll
        for (int nt = 0; nt < 4; nt++) {
            int gn = n0 + warp_n * 32 + nt * 8 + t * 2;
            if (gn < Hh) {
                if (gm < Vv) {
                    g_P[gm * Hh + gn]     = acc[mt][nt][0];
                    g_P[gm * Hh + gn + 1] = acc[mt][nt][1];
                }
                if (gm + 8 < Vv) {
                    g_P[(gm + 8) * Hh + gn]     = acc[mt][nt][2];
                    g_P[(gm + 8) * Hh + gn + 1] = acc[mt][nt][3];
                }
            }
        }
    }
}

// ---------------------------------------------------------------------------
// Kernel 3: scores[t] = b2 + sum_h w2[h] * tanh(P[words[t],h] + sup[b,h])
// one warp per token, 8 tokens/block
// ---------------------------------------------------------------------------
__global__ void k_scores(const int* __restrict__ words,
                         const float* __restrict__ w2,
                         const float* __restrict__ b2) {
    int tok = blockIdx.x * 8 + (threadIdx.x >> 5);
    int lane = threadIdx.x & 31;
    int b = tok / Ll;
    int w = words[tok];
    const float* Prow = &g_P[(long)w * Hh];
    const float* Srow = &g_sup[b * Hh];
    float acc = 0.f;
    for (int h = lane; h < Hh; h += 32) {
        float x = Prow[h] + Srow[h];
        float th;
        asm("tanh.approx.f32 %0, %1;" : "=f"(th) : "f"(x));
        acc += w2[h] * th;
    }
    #pragma unroll
    for (int o = 16; o > 0; o >>= 1) acc += __shfl_xor_sync(0xffffffffu, acc, o);
    if (lane == 0) g_score[tok] = acc + b2[0];
}

// ---------------------------------------------------------------------------
// Kernel 4: per-b softmax over L + attention-weighted sum (re-gather from emb)
// grid = B, block = 512
// ---------------------------------------------------------------------------
__global__ void k_attn_pool(const int* __restrict__ words,
                            const float* __restrict__ emb) {
    int b = blockIdx.x;
    int tid = threadIdx.x;
    __shared__ float p[Ll];
    __shared__ int sw[Ll];
    __shared__ float red[512];
    sw[tid] = words[b * Ll + tid];
    float sc = g_score[b * Ll + tid];
    red[tid] = sc;
    __syncthreads();
    for (int s = 256; s > 0; s >>= 1) {
        if (tid < s) red[tid] = fmaxf(red[tid], red[tid + s]);
        __syncthreads();
    }
    float m = red[0];
    __syncthreads();
    float e = expf(sc - m);
    p[tid] = e;
    red[tid] = e;
    __syncthreads();
    for (int s = 256; s > 0; s >>= 1) {
        if (tid < s) red[tid] += red[tid + s];
        __syncthreads();
    }
    float inv = 1.f / red[0];
    __syncthreads();
    if (tid < Dd) {
        float acc = 0.f;
        #pragma unroll 4
        for (int l = 0; l < Ll; l++)
            acc += p[l] * emb[(long)sw[l] * Dd + tid];
        g_attn[b * Dd + tid] = acc * inv;
    }
}

// ---------------------------------------------------------------------------
// Kernel 5: feat = [attn, attn, subj, obj]; out = relu(relu(feat@mw1+mb1)@mw2+mb2)
// grid = B, block = 256
// ---------------------------------------------------------------------------
__global__ void k_mlp(const float* __restrict__ mw1, const float* __restrict__ mb1,
                      const float* __restrict__ mw2, const float* __restrict__ mb2,
                      float* __restrict__ out) {
    int b = blockIdx.x;
    int tid = threadIdx.x;
    __shared__ float feat[4 * Dd];
    __shared__ float hid[Hh];
    for (int i = tid; i < Dd; i += blockDim.x) {
        float a = g_attn[b * Dd + i];
        feat[i]          = a;            // subj_attn
        feat[Dd + i]     = a;            // obj_attn (== subj_attn, source bug)
        feat[2 * Dd + i] = g_subj[b * Dd + i];
        feat[3 * Dd + i] = g_obj[b * Dd + i];
    }
    __syncthreads();
    if (tid < Hh) {
        float a = mb1[tid];
        #pragma unroll 4
        for (int k = 0; k < 4 * Dd; k++)
            a += feat[k] * mw1[k * Hh + tid];
        hid[tid] = fmaxf(a, 0.f);
    }
    __syncthreads();
    if (tid < Hh) {
        float a = mb2[tid];
        #pragma unroll 4
        for (int k = 0; k < Hh; k++)
            a += hid[k] * mw2[k * Hh + tid];
        out[b * Hh + tid] = fmaxf(a, 0.f);
    }
}

// ---------------------------------------------------------------------------
extern "C" void kernel_launch(void* const* d_in, const int* in_sizes, int n_in,
                              void* d_out, int out_size) {
    const int*   words = (const int*)d_in[0];
    const int*   spos  = (const int*)d_in[1];
    const int*   opos  = (const int*)d_in[2];
    const float* emb   = (const float*)d_in[3];
    const float* w1    = (const float*)d_in[4];
    const float* b1    = (const float*)d_in[5];
    const float* w2    = (const float*)d_in[6];
    const float* b2    = (const float*)d_in[7];
    const float* mw1   = (const float*)d_in[8];
    const float* mb1   = (const float*)d_in[9];
    const float* mw2   = (const float*)d_in[10];
    const float* mb2   = (const float*)d_in[11];
    float* out = (float*)d_out;

    k_pools<<<Bb, 320>>>(words, spos, opos, emb, w1, b1);
    dim3 gridP((Vv + GBM - 1) / GBM, (Hh + GBN - 1) / GBN);
    k_gemmP_tf32<<<gridP, 256>>>(emb, w1);
    k_scores<<<(Bb * Ll) / 8, 256>>>(words, w2, b2);
    k_attn_pool<<<Bb, 512>>>(words, emb);
    k_mlp<<<Bb, 256>>>(mw1, mb1, mw2, mb2, out);
}

// round 3
// speedup vs baseline: 1.9970x; 1.2055x over previous
#include <cuda_runtime.h>
#include <math.h>
#include <stdint.h>

#define Bb 128
#define Ll 512
#define Dd 300
#define Hh 200
#define Vv 50000

// Scratch (device globals -- no allocation allowed)
__device__ float g_P[Vv * Hh];                 // emb_table @ W1_top  (40 MB)
__device__ float g_subj_part[Bb * 4 * Dd];
__device__ float g_obj_part[Bb * 4 * Dd];
__device__ float g_subj[Bb * Dd];
__device__ float g_obj[Bb * Dd];
__device__ float g_sup[Bb * Hh];               // subj_emb @ W1_bot + b1
__device__ float g_score[Bb * Ll];
__device__ float g_prob[Bb * Ll];              // normalized softmax
__device__ float g_attn_part[Bb * 8 * Dd];

__device__ __forceinline__ void cp16(uint32_t dst, const float* src, bool v) {
    asm volatile("cp.async.cg.shared.global [%0], [%1], 16, %2;\n"
                 :: "r"(dst), "l"(src), "r"(v ? 16 : 0));
}

// ---------------------------------------------------------------------------
// Kernel 1a: partial masked max-pools, grid(B,4), 128 positions per block
// ---------------------------------------------------------------------------
__global__ void k_pools_part(const int* __restrict__ words,
                             const int* __restrict__ spos,
                             const int* __restrict__ opos,
                             const float* __restrict__ emb) {
    int b = blockIdx.x, ch = blockIdx.y;
    int tid = threadIdx.x;
    __shared__ int sl[128], ol[128];
    __shared__ int scnt, ocnt;
    if (tid == 0) { scnt = 0; ocnt = 0; }
    __syncthreads();
    int base = b * Ll + ch * 128;
    if (tid < 128) {
        int w = words[base + tid];
        if (spos[base + tid] == 0) sl[atomicAdd(&scnt, 1)] = w;
        if (opos[base + tid] == 0) ol[atomicAdd(&ocnt, 1)] = w;
    }
    __syncthreads();
    int ns = scnt, no = ocnt;
    if (tid < Dd) {
        float smax = -1e12f, omax = -1e12f;
        for (int i = 0; i < ns; i++)
            smax = fmaxf(smax, emb[(long)sl[i] * Dd + tid]);
        for (int i = 0; i < no; i++)
            omax = fmaxf(omax, emb[(long)ol[i] * Dd + tid]);
        g_subj_part[(b * 4 + ch) * Dd + tid] = smax;
        g_obj_part[(b * 4 + ch) * Dd + tid]  = omax;
    }
}

// ---------------------------------------------------------------------------
// Kernel 1b: combine partial maxes + fused sup-projection. grid = B
// ---------------------------------------------------------------------------
__global__ void k_pools_fin(const float* __restrict__ w1,
                            const float* __restrict__ b1) {
    int b = blockIdx.x;
    int tid = threadIdx.x;
    __shared__ float ssub[Dd];
    if (tid < Dd) {
        float s = -1e12f, o = -1e12f;
        #pragma unroll
        for (int c = 0; c < 4; c++) {
            s = fmaxf(s, g_subj_part[(b * 4 + c) * Dd + tid]);
            o = fmaxf(o, g_obj_part[(b * 4 + c) * Dd + tid]);
        }
        g_subj[b * Dd + tid] = s;
        g_obj[b * Dd + tid]  = o;
        ssub[tid] = s;
    }
    __syncthreads();
    if (tid < Hh) {
        float acc = b1[tid];
        #pragma unroll 4
        for (int d = 0; d < Dd; d++)
            acc += ssub[d] * w1[(Dd + d) * Hh + tid];
        g_sup[b * Hh + tid] = acc;
    }
}

// ---------------------------------------------------------------------------
// Kernel 2: P = emb_table[V,300] @ W1_top[300,200] -- tf32 MMA, cp.async
// double-buffered, block tile 128x128x16, 8 warps (2x4), warp tile 64x32.
// fp32 bits fed directly to tf32 MMA (RZ truncation).
// ---------------------------------------------------------------------------
#define GBM 128
#define GBN 128
#define GBK 16
#define ASTRIDE 20
#define BSTRIDE 136
__global__ void __launch_bounds__(256) k_gemmP_tf32(const float* __restrict__ A,
                                                    const float* __restrict__ W) {
    __shared__ float As[2][GBM][ASTRIDE];   // 20.5 KB
    __shared__ float Bs[2][GBK][BSTRIDE];   // 17.4 KB

    int m0 = blockIdx.x * GBM;
    int n0 = blockIdx.y * GBN;
    int tid = threadIdx.x;
    int wid = tid >> 5;
    int lane = tid & 31;
    int g = lane >> 2, t = lane & 3;
    int warp_m = wid >> 2;                  // 0..1
    int warp_n = wid & 3;                   // 0..3

    uint32_t asBase = (uint32_t)__cvta_generic_to_shared(&As[0][0][0]);
    uint32_t bsBase = (uint32_t)__cvta_generic_to_shared(&Bs[0][0][0]);

    float acc[4][4][4];
    #pragma unroll
    for (int i = 0; i < 4; i++)
        #pragma unroll
        for (int j = 0; j < 4; j++)
            #pragma unroll
            for (int c = 0; c < 4; c++) acc[i][j][c] = 0.f;

    const int NIT = 20;                     // 320 / 16

    // --- tile loader (cp.async, zero-fill out-of-bounds) ---
    #define LOAD_TILES(buf, k0)                                                  \
    {                                                                            \
        _Pragma("unroll")                                                        \
        for (int p = 0; p < 2; p++) {                                            \
            int idx = tid + p * 256;                                             \
            int r = idx >> 2, c = idx & 3;                                       \
            int gm = m0 + r;                                                     \
            int gk = (k0) + c * 4;                                               \
            bool v = (gm < Vv) && (gk + 4 <= Dd);                                \
            uint32_t dst = asBase + (uint32_t)((buf) * (GBM * ASTRIDE) +         \
                                               r * ASTRIDE + c * 4) * 4u;        \
            cp16(dst, A + (long)gm * Dd + gk, v);                                \
        }                                                                        \
        _Pragma("unroll")                                                        \
        for (int p = 0; p < 2; p++) {                                            \
            int idx = tid + p * 256;                                             \
            int r = idx >> 5, c = idx & 31;                                      \
            int gk = (k0) + r;                                                   \
            int gn = n0 + c * 4;                                                 \
            bool v = (gk < Dd) && (gn + 4 <= Hh);                                \
            uint32_t dst = bsBase + (uint32_t)((buf) * (GBK * BSTRIDE) +         \
                                               r * BSTRIDE + c * 4) * 4u;        \
            cp16(dst, W + (long)gk * Hh + gn, v);                                \
        }                                                                        \
        asm volatile("cp.async.commit_group;");                                  \
    }

    LOAD_TILES(0, 0);

    for (int it = 0; it < NIT; it++) {
        asm volatile("cp.async.wait_group 0;");
        __syncthreads();
        if (it + 1 < NIT) LOAD_TILES((it + 1) & 1, (it + 1) * GBK);
        int buf = it & 1;

        #pragma unroll
        for (int ks = 0; ks < 2; ks++) {
            int kl = ks * 8;
            uint32_t ua[4][4], ub[4][2];
            #pragma unroll
            for (int mt = 0; mt < 4; mt++) {
                int mr = warp_m * 64 + mt * 16;
                ua[mt][0] = __float_as_uint(As[buf][mr + g][kl + t]);
                ua[mt][1] = __float_as_uint(As[buf][mr + g + 8][kl + t]);
                ua[mt][2] = __float_as_uint(As[buf][mr + g][kl + t + 4]);
                ua[mt][3] = __float_as_uint(As[buf][mr + g + 8][kl + t + 4]);
            }
            #pragma unroll
            for (int nt = 0; nt < 4; nt++) {
                int nc = warp_n * 32 + nt * 8;
                ub[nt][0] = __float_as_uint(Bs[buf][kl + t][nc + g]);
                ub[nt][1] = __float_as_uint(Bs[buf][kl + t + 4][nc + g]);
            }
            #pragma unroll
            for (int mt = 0; mt < 4; mt++)
                #pragma unroll
                for (int nt = 0; nt < 4; nt++)
                    asm volatile(
                        "mma.sync.aligned.m16n8k8.row.col.f32.tf32.tf32.f32 "
                        "{%0,%1,%2,%3}, {%4,%5,%6,%7}, {%8,%9}, {%0,%1,%2,%3};"
                        : "+f"(acc[mt][nt][0]), "+f"(acc[mt][nt][1]),
                          "+f"(acc[mt][nt][2]), "+f"(acc[mt][nt][3])
                        : "r"(ua[mt][0]), "r"(ua[mt][1]), "r"(ua[mt][2]), "r"(ua[mt][3]),
                          "r"(ub[nt][0]), "r"(ub[nt][1]));
        }
        __syncthreads();
    }

    #pragma unroll
    for (int mt = 0; mt < 4; mt++) {
        long gm = m0 + warp_m * 64 + mt * 16 + g;
        #pragma unroll
        for (int nt = 0; nt < 4; nt++) {
            int gn = n0 + warp_n * 32 + nt * 8 + t * 2;
            if (gn < Hh) {
                if (gm < Vv) {
                    g_P[gm * Hh + gn]     = acc[mt][nt][0];
                    g_P[gm * Hh + gn + 1] = acc[mt][nt][1];
                }
                if (gm + 8 < Vv) {
                    g_P[(gm + 8) * Hh + gn]     = acc[mt][nt][2];
                    g_P[(gm + 8) * Hh + gn + 1] = acc[mt][nt][3];
                }
            }
        }
    }
}

// ---------------------------------------------------------------------------
// Kernel 3: scores[t] = b2 + sum_h w2[h] * tanh(P[words[t],h] + sup[b,h])
// ---------------------------------------------------------------------------
__global__ void k_scores(const int* __restrict__ words,
                         const float* __restrict__ w2,
                         const float* __restrict__ b2) {
    int tok = blockIdx.x * 8 + (threadIdx.x >> 5);
    int lane = threadIdx.x & 31;
    int b = tok / Ll;
    int w = words[tok];
    const float* Prow = &g_P[(long)w * Hh];
    const float* Srow = &g_sup[b * Hh];
    float acc = 0.f;
    for (int h = lane; h < Hh; h += 32) {
        float x = Prow[h] + Srow[h];
        float th;
        asm("tanh.approx.f32 %0, %1;" : "=f"(th) : "f"(x));
        acc += w2[h] * th;
    }
    #pragma unroll
    for (int o = 16; o > 0; o >>= 1) acc += __shfl_xor_sync(0xffffffffu, acc, o);
    if (lane == 0) g_score[tok] = acc + b2[0];
}

// ---------------------------------------------------------------------------
// Kernel 4a: per-b softmax -> normalized probs. grid = B, block = 512
// ---------------------------------------------------------------------------
__global__ void k_softmax() {
    int b = blockIdx.x;
    int tid = threadIdx.x;
    __shared__ float red[512];
    float sc = g_score[b * Ll + tid];
    red[tid] = sc;
    __syncthreads();
    for (int s = 256; s > 0; s >>= 1) {
        if (tid < s) red[tid] = fmaxf(red[tid], red[tid + s]);
        __syncthreads();
    }
    float m = red[0];
    __syncthreads();
    float e = expf(sc - m);
    red[tid] = e;
    __syncthreads();
    for (int s = 256; s > 0; s >>= 1) {
        if (tid < s) red[tid] += red[tid + s];
        __syncthreads();
    }
    g_prob[b * Ll + tid] = e / red[0];
}

// ---------------------------------------------------------------------------
// Kernel 4b: partial attention-weighted sum, grid(B,8), 64 positions each
// ---------------------------------------------------------------------------
__global__ void k_attn_part(const int* __restrict__ words,
                            const float* __restrict__ emb) {
    int b = blockIdx.x, ch = blockIdx.y;
    int tid = threadIdx.x;
    __shared__ float p[64];
    __shared__ int sw[64];
    int base = b * Ll + ch * 64;
    if (tid < 64) {
        p[tid] = g_prob[base + tid];
        sw[tid] = words[base + tid];
    }
    __syncthreads();
    if (tid < Dd) {
        float acc = 0.f;
        #pragma unroll 4
        for (int i = 0; i < 64; i++)
            acc += p[i] * emb[(long)sw[i] * Dd + tid];
        g_attn_part[(b * 8 + ch) * Dd + tid] = acc;
    }
}

// ---------------------------------------------------------------------------
// Kernel 5: feat = [attn, attn, subj, obj]; 2-layer relu MLP. grid = B
// ---------------------------------------------------------------------------
__global__ void k_mlp(const float* __restrict__ mw1, const float* __restrict__ mb1,
                      const float* __restrict__ mw2, const float* __restrict__ mb2,
                      float* __restrict__ out) {
    int b = blockIdx.x;
    int tid = threadIdx.x;
    __shared__ float feat[4 * Dd];
    __shared__ float hid[Hh];
    for (int i = tid; i < Dd; i += blockDim.x) {
        float a = 0.f;
        #pragma unroll
        for (int c = 0; c < 8; c++)
            a += g_attn_part[(b * 8 + c) * Dd + i];
        feat[i]          = a;            // subj_attn
        feat[Dd + i]     = a;            // obj_attn (== subj_attn, source bug)
        feat[2 * Dd + i] = g_subj[b * Dd + i];
        feat[3 * Dd + i] = g_obj[b * Dd + i];
    }
    __syncthreads();
    if (tid < Hh) {
        float a = mb1[tid];
        #pragma unroll 4
        for (int k = 0; k < 4 * Dd; k++)
            a += feat[k] * mw1[k * Hh + tid];
        hid[tid] = fmaxf(a, 0.f);
    }
    __syncthreads();
    if (tid < Hh) {
        float a = mb2[tid];
        #pragma unroll 4
        for (int k = 0; k < Hh; k++)
            a += hid[k] * mw2[k * Hh + tid];
        out[b * Hh + tid] = fmaxf(a, 0.f);
    }
}

// ---------------------------------------------------------------------------
extern "C" void kernel_launch(void* const* d_in, const int* in_sizes, int n_in,
                              void* d_out, int out_size) {
    const int*   words = (const int*)d_in[0];
    const int*   spos  = (const int*)d_in[1];
    const int*   opos  = (const int*)d_in[2];
    const float* emb   = (const float*)d_in[3];
    const float* w1    = (const float*)d_in[4];
    const float* b1    = (const float*)d_in[5];
    const float* w2    = (const float*)d_in[6];
    const float* b2    = (const float*)d_in[7];
    const float* mw1   = (const float*)d_in[8];
    const float* mb1   = (const float*)d_in[9];
    const float* mw2   = (const float*)d_in[10];
    const float* mb2   = (const float*)d_in[11];
    float* out = (float*)d_out;

    dim3 gridP((Vv + GBM - 1) / GBM, (Hh + GBN - 1) / GBN);
    k_gemmP_tf32<<<gridP, 256>>>(emb, w1);
    k_pools_part<<<dim3(Bb, 4), 320>>>(words, spos, opos, emb);
    k_pools_fin<<<Bb, 320>>>(w1, b1);
    k_scores<<<(Bb * Ll) / 8, 256>>>(words, w2, b2);
    k_softmax<<<Bb, 512>>>();
    k_attn_part<<<dim3(Bb, 8), 320>>>(words, emb);
    k_mlp<<<Bb, 256>>>(mw1, mb1, mw2, mb2, out);
}

// round 5
// speedup vs baseline: 2.0617x; 1.0324x over previous
#include <cuda_runtime.h>
#include <cuda_fp16.h>
#include <math.h>
#include <stdint.h>

#define Bb 128
#define Ll 512
#define Dd 300
#define Hh 200
#define Vv 50000

#define MPAD 50048      // Vv padded to 128
#define KPAD 320        // Dd padded to 32
#define NPAD 256        // Hh padded to 128

// Scratch (device globals -- no allocation allowed)
__device__ float  g_P[Vv * Hh];              // emb_table @ W1_top  (40 MB)
__device__ __half g_Ah[MPAD * KPAD];         // fp16 padded emb_table (32 MB)
__device__ __half g_Wh[NPAD * KPAD];         // fp16 W1_top^T, n-major
__device__ float  g_subj_part[Bb * 4 * Dd];
__device__ float  g_obj_part[Bb * 4 * Dd];
__device__ float  g_subj[Bb * Dd];
__device__ float  g_obj[Bb * Dd];
__device__ float  g_sup[Bb * Hh];
__device__ float  g_score[Bb * Ll];
__device__ float  g_prob[Bb * Ll];
__device__ float  g_attn_part[Bb * 8 * Dd];

__device__ __forceinline__ void cp16(uint32_t dst, const void* src) {
    asm volatile("cp.async.cg.shared.global [%0], [%1], 16;\n"
                 :: "r"(dst), "l"(src));
}

// ---------------------------------------------------------------------------
// Kernel 0a: emb_table f32 -> padded f16 image g_Ah
// ---------------------------------------------------------------------------
__global__ void k_prepA(const float* __restrict__ emb) {
    int idx = blockIdx.x * blockDim.x + threadIdx.x;     // half2 index
    int total = MPAD * (KPAD / 2);
    for (; idx < total; idx += gridDim.x * blockDim.x) {
        int row = idx / (KPAD / 2);
        int c2 = idx % (KPAD / 2);
        __half2 v = __float2half2_rn(0.f);
        if (row < Vv && 2 * c2 + 1 < Dd) {
            const float* p = emb + (long)row * Dd + 2 * c2;
            v = __floats2half2_rn(p[0], p[1]);
        }
        *reinterpret_cast<__half2*>(&g_Ah[(long)row * KPAD + 2 * c2]) = v;
    }
}

// ---------------------------------------------------------------------------
// Kernel 0b: W1_top f32 -> transposed padded f16 image g_Wh[n][k]
// ---------------------------------------------------------------------------
__global__ void k_prepW(const float* __restrict__ w1) {
    int idx = blockIdx.x * blockDim.x + threadIdx.x;
    int total = NPAD * KPAD;
    for (; idx < total; idx += gridDim.x * blockDim.x) {
        int n = idx / KPAD;
        int k = idx % KPAD;
        float v = (n < Hh && k < Dd) ? w1[k * Hh + n] : 0.f;
        g_Wh[idx] = __float2half(v);
    }
}

// ---------------------------------------------------------------------------
// Kernel 2: P = emb @ W1_top via fp16 mma.sync.m16n8k16, fp32 accumulate.
// Tiles 128x128x32(half), cp.async double-buffered, 8 warps (2x4), 64x32/warp.
// All loads unguarded (padded images).
// ---------------------------------------------------------------------------
#define GBM 128
#define GBN 128
#define GBKH 32
#define HSTR 40
__global__ void __launch_bounds__(256) k_gemm_fp16() {
    __shared__ __half Ah[2][GBM][HSTR];     // 10 KB each buf
    __shared__ __half Bh[2][GBN][HSTR];

    int m0 = blockIdx.x * GBM;
    int n0 = blockIdx.y * GBN;
    int tid = threadIdx.x;
    int wid = tid >> 5;
    int lane = tid & 31;
    int g = lane >> 2, t = lane & 3;
    int warp_m = wid >> 2;                  // 0..1
    int warp_n = wid & 3;                   // 0..3

    uint32_t aBase = (uint32_t)__cvta_generic_to_shared(&Ah[0][0][0]);
    uint32_t bBase = (uint32_t)__cvta_generic_to_shared(&Bh[0][0][0]);

    float acc[4][4][4];
    #pragma unroll
    for (int i = 0; i < 4; i++)
        #pragma unroll
        for (int j = 0; j < 4; j++)
            #pragma unroll
            for (int c = 0; c < 4; c++) acc[i][j][c] = 0.f;

    const int NIT = KPAD / GBKH;            // 10
    int seg = tid & 3;                      // 16B segment (8 halves)
    int r0 = tid >> 2;                      // 0..63

    #define LOAD_TILES(buf, k0)                                               \
    {                                                                         \
        _Pragma("unroll")                                                     \
        for (int p = 0; p < 2; p++) {                                         \
            int r = r0 + p * 64;                                              \
            uint32_t dst = aBase + (uint32_t)((buf) * (GBM * HSTR) +          \
                                              r * HSTR + seg * 8) * 2u;       \
            cp16(dst, g_Ah + (long)(m0 + r) * KPAD + (k0) + seg * 8);         \
        }                                                                     \
        _Pragma("unroll")                                                     \
        for (int p = 0; p < 2; p++) {                                         \
            int r = r0 + p * 64;                                              \
            uint32_t dst = bBase + (uint32_t)((buf) * (GBN * HSTR) +          \
                                              r * HSTR + seg * 8) * 2u;       \
            cp16(dst, g_Wh + (long)(n0 + r) * KPAD + (k0) + seg * 8);         \
        }                                                                     \
        asm volatile("cp.async.commit_group;");                               \
    }

    LOAD_TILES(0, 0);

    for (int it = 0; it < NIT; it++) {
        asm volatile("cp.async.wait_group 0;");
        __syncthreads();
        if (it + 1 < NIT) LOAD_TILES((it + 1) & 1, (it + 1) * GBKH);
        int buf = it & 1;

        #pragma unroll
        for (int ks = 0; ks < 2; ks++) {
            int kl = ks * 16;
            uint32_t ua[4][4], ub[4][2];
            #pragma unroll
            for (int mt = 0; mt < 4; mt++) {
                int mr = warp_m * 64 + mt * 16;
                ua[mt][0] = *(const uint32_t*)&Ah[buf][mr + g][kl + 2 * t];
                ua[mt][1] = *(const uint32_t*)&Ah[buf][mr + g + 8][kl + 2 * t];
                ua[mt][2] = *(const uint32_t*)&Ah[buf][mr + g][kl + 2 * t + 8];
                ua[mt][3] = *(const uint32_t*)&Ah[buf][mr + g + 8][kl + 2 * t + 8];
            }
            #pragma unroll
            for (int nt = 0; nt < 4; nt++) {
                int nc = warp_n * 32 + nt * 8;
                ub[nt][0] = *(const uint32_t*)&Bh[buf][nc + g][kl + 2 * t];
                ub[nt][1] = *(const uint32_t*)&Bh[buf][nc + g][kl + 2 * t + 8];
            }
            #pragma unroll
            for (int mt = 0; mt < 4; mt++)
                #pragma unroll
                for (int nt = 0; nt < 4; nt++)
                    asm volatile(
                        "mma.sync.aligned.m16n8k16.row.col.f32.f16.f16.f32 "
                        "{%0,%1,%2,%3}, {%4,%5,%6,%7}, {%8,%9}, {%0,%1,%2,%3};"
                        : "+f"(acc[mt][nt][0]), "+f"(acc[mt][nt][1]),
                          "+f"(acc[mt][nt][2]), "+f"(acc[mt][nt][3])
                        : "r"(ua[mt][0]), "r"(ua[mt][1]), "r"(ua[mt][2]), "r"(ua[mt][3]),
                          "r"(ub[nt][0]), "r"(ub[nt][1]));
        }
        __syncthreads();
    }

    #pragma unroll
    for (int mt = 0; mt < 4; mt++) {
        long gm = m0 + warp_m * 64 + mt * 16 + g;
        #pragma unroll
        for (int nt = 0; nt < 4; nt++) {
            int gn = n0 + warp_n * 32 + nt * 8 + t * 2;
            if (gn < Hh) {
                if (gm < Vv) {
                    g_P[gm * Hh + gn]     = acc[mt][nt][0];
                    g_P[gm * Hh + gn + 1] = acc[mt][nt][1];
                }
                if (gm + 8 < Vv) {
                    g_P[(gm + 8) * Hh + gn]     = acc[mt][nt][2];
                    g_P[(gm + 8) * Hh + gn + 1] = acc[mt][nt][3];
                }
            }
        }
    }
}

// ---------------------------------------------------------------------------
// Kernel 1a: partial masked max-pools, grid(B,4), 128 positions per block
// ---------------------------------------------------------------------------
__global__ void k_pools_part(const int* __restrict__ words,
                             const int* __restrict__ spos,
                             const int* __restrict__ opos,
                             const float* __restrict__ emb) {
    int b = blockIdx.x, ch = blockIdx.y;
    int tid = threadIdx.x;
    __shared__ int sl[128], ol[128];
    __shared__ int scnt, ocnt;
    if (tid == 0) { scnt = 0; ocnt = 0; }
    __syncthreads();
    int base = b * Ll + ch * 128;
    if (tid < 128) {
        int w = words[base + tid];
        if (spos[base + tid] == 0) sl[atomicAdd(&scnt, 1)] = w;
        if (opos[base + tid] == 0) ol[atomicAdd(&ocnt, 1)] = w;
    }
    __syncthreads();
    int ns = scnt, no = ocnt;
    if (tid < Dd) {
        float smax = -1e12f, omax = -1e12f;
        for (int i = 0; i < ns; i++)
            smax = fmaxf(smax, emb[(long)sl[i] * Dd + tid]);
        for (int i = 0; i < no; i++)
            omax = fmaxf(omax, emb[(long)ol[i] * Dd + tid]);
        g_subj_part[(b * 4 + ch) * Dd + tid] = smax;
        g_obj_part[(b * 4 + ch) * Dd + tid]  = omax;
    }
}

// ---------------------------------------------------------------------------
// Kernel 1b: combine partial maxes + fused sup-projection. grid = B
// ---------------------------------------------------------------------------
__global__ void k_pools_fin(const float* __restrict__ w1,
                            const float* __restrict__ b1) {
    int b = blockIdx.x;
    int tid = threadIdx.x;
    __shared__ float ssub[Dd];
    if (tid < Dd) {
        float s = -1e12f, o = -1e12f;
        #pragma unroll
        for (int c = 0; c < 4; c++) {
            s = fmaxf(s, g_subj_part[(b * 4 + c) * Dd + tid]);
            o = fmaxf(o, g_obj_part[(b * 4 + c) * Dd + tid]);
        }
        g_subj[b * Dd + tid] = s;
        g_obj[b * Dd + tid]  = o;
        ssub[tid] = s;
    }
    __syncthreads();
    if (tid < Hh) {
        float acc = b1[tid];
        #pragma unroll 4
        for (int d = 0; d < Dd; d++)
            acc += ssub[d] * w1[(Dd + d) * Hh + tid];
        g_sup[b * Hh + tid] = acc;
    }
}

// ---------------------------------------------------------------------------
// Kernel 3: scores[t] = b2 + sum_h w2[h] * tanh(P[words[t],h] + sup[b,h])
// ---------------------------------------------------------------------------
__global__ void k_scores(const int* __restrict__ words,
                         const float* __restrict__ w2,
                         const float* __restrict__ b2) {
    int tok = blockIdx.x * 8 + (threadIdx.x >> 5);
    int lane = threadIdx.x & 31;
    int b = tok / Ll;
    int w = words[tok];
    const float* Prow = &g_P[(long)w * Hh];
    const float* Srow = &g_sup[b * Hh];
    float acc = 0.f;
    for (int h = lane; h < Hh; h += 32) {
        float x = Prow[h] + Srow[h];
        float th;
        asm("tanh.approx.f32 %0, %1;" : "=f"(th) : "f"(x));
        acc += w2[h] * th;
    }
    #pragma unroll
    for (int o = 16; o > 0; o >>= 1) acc += __shfl_xor_sync(0xffffffffu, acc, o);
    if (lane == 0) g_score[tok] = acc + b2[0];
}

// ---------------------------------------------------------------------------
// Kernel 4a: per-b softmax -> normalized probs. grid = B, block = 512
// ---------------------------------------------------------------------------
__global__ void k_softmax() {
    int b = blockIdx.x;
    int tid = threadIdx.x;
    __shared__ float red[512];
    float sc = g_score[b * Ll + tid];
    red[tid] = sc;
    __syncthreads();
    for (int s = 256; s > 0; s >>= 1) {
        if (tid < s) red[tid] = fmaxf(red[tid], red[tid + s]);
        __syncthreads();
    }
    float m = red[0];
    __syncthreads();
    float e = expf(sc - m);
    red[tid] = e;
    __syncthreads();
    for (int s = 256; s > 0; s >>= 1) {
        if (tid < s) red[tid] += red[tid + s];
        __syncthreads();
    }
    g_prob[b * Ll + tid] = e / red[0];
}

// ---------------------------------------------------------------------------
// Kernel 4b: partial attention-weighted sum, grid(B,8), 64 positions each
// ---------------------------------------------------------------------------
__global__ void k_attn_part(const int* __restrict__ words,
                            const float* __restrict__ emb) {
    int b = blockIdx.x, ch = blockIdx.y;
    int tid = threadIdx.x;
    __shared__ float p[64];
    __shared__ int sw[64];
    int base = b * Ll + ch * 64;
    if (tid < 64) {
        p[tid] = g_prob[base + tid];
        sw[tid] = words[base + tid];
    }
    __syncthreads();
    if (tid < Dd) {
        float acc = 0.f;
        #pragma unroll 4
        for (int i = 0; i < 64; i++)
            acc += p[i] * emb[(long)sw[i] * Dd + tid];
        g_attn_part[(b * 8 + ch) * Dd + tid] = acc;
    }
}

// ---------------------------------------------------------------------------
// Kernel 5: feat = [attn, attn, subj, obj]; 2-layer relu MLP. grid = B
// ---------------------------------------------------------------------------
__global__ void k_mlp(const float* __restrict__ mw1, const float* __restrict__ mb1,
                      const float* __restrict__ mw2, const float* __restrict__ mb2,
                      float* __restrict__ out) {
    int b = blockIdx.x;
    int tid = threadIdx.x;
    __shared__ float feat[4 * Dd];
    __shared__ float hid[Hh];
    for (int i = tid; i < Dd; i += blockDim.x) {
        float a = 0.f;
        #pragma unroll
        for (int c = 0; c < 8; c++)
            a += g_attn_part[(b * 8 + c) * Dd + i];
        feat[i]          = a;            // subj_attn
        feat[Dd + i]     = a;            // obj_attn (== subj_attn, source bug)
        feat[2 * Dd + i] = g_subj[b * Dd + i];
        feat[3 * Dd + i] = g_obj[b * Dd + i];
    }
    __syncthreads();
    if (tid < Hh) {
        float a = mb1[tid];
        #pragma unroll 4
        for (int k = 0; k < 4 * Dd; k++)
            a += feat[k] * mw1[k * Hh + tid];
        hid[tid] = fmaxf(a, 0.f);
    }
    __syncthreads();
    if (tid < Hh) {
        float a = mb2[tid];
        #pragma unroll 4
        for (int k = 0; k < Hh; k++)
            a += hid[k] * mw2[k * Hh + tid];
        out[b * Hh + tid] = fmaxf(a, 0.f);
    }
}

// ---------------------------------------------------------------------------
extern "C" void kernel_launch(void* const* d_in, const int* in_sizes, int n_in,
                              void* d_out, int out_size) {
    const int*   words = (const int*)d_in[0];
    const int*   spos  = (const int*)d_in[1];
    const int*   opos  = (const int*)d_in[2];
    const float* emb   = (const float*)d_in[3];
    const float* w1    = (const float*)d_in[4];
    const float* b1    = (const float*)d_in[5];
    const float* w2    = (const float*)d_in[6];
    const float* b2    = (const float*)d_in[7];
    const float* mw1   = (const float*)d_in[8];
    const float* mb1   = (const float*)d_in[9];
    const float* mw2   = (const float*)d_in[10];
    const float* mb2   = (const float*)d_in[11];
    float* out = (float*)d_out;

    k_prepA<<<1184, 256>>>(emb);
    k_prepW<<<40, 256>>>(w1);
    dim3 gridP(MPAD / GBM, NPAD / GBN);
    k_gemm_fp16<<<gridP, 256>>>();
    k_pools_part<<<dim3(Bb, 4), 320>>>(words, spos, opos, emb);
    k_pools_fin<<<Bb, 320>>>(w1, b1);
    k_scores<<<(Bb * Ll) / 8, 256>>>(words, w2, b2);
    k_softmax<<<Bb, 512>>>();
    k_attn_part<<<dim3(Bb, 8), 320>>>(words, emb);
    k_mlp<<<Bb, 256>>>(mw1, mb1, mw2, mb2, out);
}

// round 6
// speedup vs baseline: 3.3825x; 1.6406x over previous
#include <cuda_runtime.h>
#include <cuda_fp16.h>
#include <math.h>
#include <stdint.h>

#define Bb 128
#define Ll 512
#define Dd 300
#define Hh 200
#define Vv 50000

#define KPAD 320        // Dd padded to 32
#define NPADW 224       // Hh padded to 224 (= 4 warps * 56)

// Scratch (device globals -- no allocation allowed)
__device__ __half g_Wh[NPADW * KPAD];        // fp16 W1_top^T, n-major, zero-padded
__device__ float  g_subj_part[Bb * 4 * Dd];
__device__ float  g_obj_part[Bb * 4 * Dd];
__device__ float  g_subj[Bb * Dd];
__device__ float  g_obj[Bb * Dd];
__device__ float  g_sup[Bb * Hh];
__device__ float  g_score[Bb * Ll];
__device__ float  g_prob[Bb * Ll];
__device__ float  g_attn_part[Bb * 8 * Dd];

__device__ __forceinline__ void cp16(uint32_t dst, const void* src) {
    asm volatile("cp.async.cg.shared.global [%0], [%1], 16;\n"
                 :: "r"(dst), "l"(src));
}
__device__ __forceinline__ void cp16p(uint32_t dst, const void* src, bool v) {
    asm volatile("cp.async.cg.shared.global [%0], [%1], 16, %2;\n"
                 :: "r"(dst), "l"(src), "r"(v ? 16 : 0));
}
__device__ __forceinline__ uint32_t pkh2(float a, float b) {
    __half2 h = __floats2half2_rn(a, b);
    return *reinterpret_cast<uint32_t*>(&h);
}

// ---------------------------------------------------------------------------
// Kernel 0: W1_top f32 -> transposed padded f16 image g_Wh[n][k]
// ---------------------------------------------------------------------------
__global__ void k_prepW(const float* __restrict__ w1) {
    int idx = blockIdx.x * blockDim.x + threadIdx.x;
    int total = NPADW * KPAD;
    for (; idx < total; idx += gridDim.x * blockDim.x) {
        int n = idx / KPAD;
        int k = idx % KPAD;
        float v = (n < Hh && k < Dd) ? w1[k * Hh + n] : 0.f;
        g_Wh[idx] = __float2half(v);
    }
}

// ---------------------------------------------------------------------------
// Kernel 1a: partial masked max-pools, grid(B,4), 128 positions per block
// ---------------------------------------------------------------------------
__global__ void k_pools_part(const int* __restrict__ words,
                             const int* __restrict__ spos,
                             const int* __restrict__ opos,
                             const float* __restrict__ emb) {
    int b = blockIdx.x, ch = blockIdx.y;
    int tid = threadIdx.x;
    __shared__ int sl[128], ol[128];
    __shared__ int scnt, ocnt;
    if (tid == 0) { scnt = 0; ocnt = 0; }
    __syncthreads();
    int base = b * Ll + ch * 128;
    if (tid < 128) {
        int w = words[base + tid];
        if (spos[base + tid] == 0) sl[atomicAdd(&scnt, 1)] = w;
        if (opos[base + tid] == 0) ol[atomicAdd(&ocnt, 1)] = w;
    }
    __syncthreads();
    int ns = scnt, no = ocnt;
    if (tid < Dd) {
        float smax = -1e12f, omax = -1e12f;
        for (int i = 0; i < ns; i++)
            smax = fmaxf(smax, emb[(long)sl[i] * Dd + tid]);
        for (int i = 0; i < no; i++)
            omax = fmaxf(omax, emb[(long)ol[i] * Dd + tid]);
        g_subj_part[(b * 4 + ch) * Dd + tid] = smax;
        g_obj_part[(b * 4 + ch) * Dd + tid]  = omax;
    }
}

// ---------------------------------------------------------------------------
// Kernel 1b: combine partial maxes + fused sup-projection. grid = B
// ---------------------------------------------------------------------------
__global__ void k_pools_fin(const float* __restrict__ w1,
                            const float* __restrict__ b1) {
    int b = blockIdx.x;
    int tid = threadIdx.x;
    __shared__ float ssub[Dd];
    if (tid < Dd) {
        float s = -1e12f, o = -1e12f;
        #pragma unroll
        for (int c = 0; c < 4; c++) {
            s = fmaxf(s, g_subj_part[(b * 4 + c) * Dd + tid]);
            o = fmaxf(o, g_obj_part[(b * 4 + c) * Dd + tid]);
        }
        g_subj[b * Dd + tid] = s;
        g_obj[b * Dd + tid]  = o;
        ssub[tid] = s;
    }
    __syncthreads();
    if (tid < Hh) {
        float acc = b1[tid];
        #pragma unroll 4
        for (int d = 0; d < Dd; d++)
            acc += ssub[d] * w1[(Dd + d) * Hh + tid];
        g_sup[b * Hh + tid] = acc;
    }
}

// ---------------------------------------------------------------------------
// Kernel 2 (FUSED): per 128-token tile, gather emb rows (fp32, cp.async,
// double-buffered K chunks of 32), fp16 mma.sync m16n8k16 against W1_top^T
// (224 padded N), then score[tok] = b2 + sum_n w2[n]*tanh(hid[tok,n]+sup[b,n]).
// grid (B, 4), 256 threads, 8 warps as 2(m) x 4(n), warp tile 64x56.
// ---------------------------------------------------------------------------
// dynamic smem layout (bytes):
#define FSM_A    0              // float A[2][128][36] = 36864
#define FSM_B    36864          // half  B[2][224][40] = 35840
#define FSM_WD   72704          // int   wds[128]      = 512
#define FSM_SUP  73216          // float sup[224]      = 896
#define FSM_W2   74112          // float w2s[224]      = 896
#define FSM_SC   75008          // float sc[128]       = 512
#define FSM_TOTAL 75520

__global__ void __launch_bounds__(256) k_fused(const int* __restrict__ words,
                                               const float* __restrict__ emb,
                                               const float* __restrict__ w2,
                                               const float* __restrict__ b2) {
    extern __shared__ char sm[];
    uint32_t smBase;
    asm("{ .reg .u64 t; cvta.to.shared.u64 t, %1; cvt.u32.u64 %0, t; }"
        : "=r"(smBase) : "l"(sm));

    float* Af  = (float*)(sm + FSM_A);        // [2][128][36]
    __half* Bh = (__half*)(sm + FSM_B);       // [2][224][40]
    int*   wds = (int*)(sm + FSM_WD);
    float* sup = (float*)(sm + FSM_SUP);
    float* w2s = (float*)(sm + FSM_W2);
    float* sc  = (float*)(sm + FSM_SC);

    int b = blockIdx.x, ch = blockIdx.y;
    int tid = threadIdx.x;
    int wid = tid >> 5;
    int lane = tid & 31;
    int g = lane >> 2, t = lane & 3;
    int warp_m = wid >> 2;                    // 0..1
    int warp_n = wid & 3;                     // 0..3

    float bias = b2[0];
    if (tid < 128) {
        wds[tid] = words[b * Ll + ch * 128 + tid];
        sc[tid] = bias;
    }
    if (tid < NPADW) {
        sup[tid] = (tid < Hh) ? g_sup[b * Hh + tid] : 0.f;
        w2s[tid] = (tid < Hh) ? w2[tid] : 0.f;
    }
    __syncthreads();

    int arow = tid >> 1;                      // 0..127
    int s0 = (tid & 1) * 4;                   // first 16B segment
    const float* rowsrc = emb + (long)wds[arow] * Dd;

    #define F_LOAD(buf, c)                                                    \
    {                                                                         \
        int kb = (c) * 32;                                                    \
        _Pragma("unroll")                                                     \
        for (int s = 0; s < 4; s++) {                                         \
            int seg = s0 + s;                                                 \
            bool v = (kb + seg * 4 + 4 <= Dd);                                \
            uint32_t dst = smBase + FSM_A +                                   \
                (uint32_t)((buf) * 4608 + arow * 36 + seg * 4) * 4u;          \
            cp16p(dst, rowsrc + kb + seg * 4, v);                             \
        }                                                                     \
        _Pragma("unroll")                                                     \
        for (int p = 0; p < 4; p++) {                                         \
            int idx = tid + p * 256;                                          \
            if (idx < 896) {                                                  \
                int r = idx >> 2, sg = idx & 3;                               \
                uint32_t dst = smBase + FSM_B +                               \
                    (uint32_t)((buf) * 8960 + r * 40 + sg * 8) * 2u;          \
                cp16(dst, g_Wh + r * KPAD + (c) * 32 + sg * 8);               \
            }                                                                 \
        }                                                                     \
        asm volatile("cp.async.commit_group;");                               \
    }

    float acc[4][7][4];
    #pragma unroll
    for (int i = 0; i < 4; i++)
        #pragma unroll
        for (int j = 0; j < 7; j++)
            #pragma unroll
            for (int c = 0; c < 4; c++) acc[i][j][c] = 0.f;

    F_LOAD(0, 0);

    const int NIT = KPAD / 32;                // 10
    for (int it = 0; it < NIT; it++) {
        asm volatile("cp.async.wait_group 0;");
        __syncthreads();
        if (it + 1 < NIT) F_LOAD((it + 1) & 1, it + 1);
        int buf = it & 1;
        const float* Afb = Af + buf * 4608;
        const __half* Bhb = Bh + buf * 8960;

        #pragma unroll
        for (int ks = 0; ks < 2; ks++) {
            int kl = ks * 16;
            uint32_t ua[4][4], ub[7][2];
            #pragma unroll
            for (int mt = 0; mt < 4; mt++) {
                int mr = warp_m * 64 + mt * 16;
                const float* r1 = Afb + (mr + g) * 36 + kl + 2 * t;
                const float* r2 = Afb + (mr + g + 8) * 36 + kl + 2 * t;
                ua[mt][0] = pkh2(r1[0], r1[1]);
                ua[mt][1] = pkh2(r2[0], r2[1]);
                ua[mt][2] = pkh2(r1[8], r1[9]);
                ua[mt][3] = pkh2(r2[8], r2[9]);
            }
            #pragma unroll
            for (int nt = 0; nt < 7; nt++) {
                int nc = warp_n * 56 + nt * 8;
                ub[nt][0] = *(const uint32_t*)&Bhb[(nc + g) * 40 + kl + 2 * t];
                ub[nt][1] = *(const uint32_t*)&Bhb[(nc + g) * 40 + kl + 2 * t + 8];
            }
            #pragma unroll
            for (int mt = 0; mt < 4; mt++)
                #pragma unroll
                for (int nt = 0; nt < 7; nt++)
                    asm volatile(
                        "mma.sync.aligned.m16n8k16.row.col.f32.f16.f16.f32 "
                        "{%0,%1,%2,%3}, {%4,%5,%6,%7}, {%8,%9}, {%0,%1,%2,%3};"
                        : "+f"(acc[mt][nt][0]), "+f"(acc[mt][nt][1]),
                          "+f"(acc[mt][nt][2]), "+f"(acc[mt][nt][3])
                        : "r"(ua[mt][0]), "r"(ua[mt][1]), "r"(ua[mt][2]), "r"(ua[mt][3]),
                          "r"(ub[nt][0]), "r"(ub[nt][1]));
        }
        __syncthreads();
    }

    // epilogue: score contributions. rows r1 = wm*64+mt*16+g, r2 = r1+8
    #pragma unroll
    for (int mt = 0; mt < 4; mt++) {
        int r1 = warp_m * 64 + mt * 16 + g;
        float rs0 = 0.f, rs1 = 0.f;
        #pragma unroll
        for (int nt = 0; nt < 7; nt++) {
            int col = warp_n * 56 + nt * 8 + 2 * t;
            float wa = w2s[col], wb = w2s[col + 1];
            float sa = sup[col], sb = sup[col + 1];
            float t0, t1, t2, t3;
            asm("tanh.approx.f32 %0, %1;" : "=f"(t0) : "f"(acc[mt][nt][0] + sa));
            asm("tanh.approx.f32 %0, %1;" : "=f"(t1) : "f"(acc[mt][nt][1] + sb));
            asm("tanh.approx.f32 %0, %1;" : "=f"(t2) : "f"(acc[mt][nt][2] + sa));
            asm("tanh.approx.f32 %0, %1;" : "=f"(t3) : "f"(acc[mt][nt][3] + sb));
            rs0 += wa * t0 + wb * t1;
            rs1 += wa * t2 + wb * t3;
        }
        atomicAdd(&sc[r1], rs0);
        atomicAdd(&sc[r1 + 8], rs1);
    }
    __syncthreads();
    if (tid < 128)
        g_score[b * Ll + ch * 128 + tid] = sc[tid];
}

// ---------------------------------------------------------------------------
// Kernel 4a: per-b softmax -> normalized probs. grid = B, block = 512
// ---------------------------------------------------------------------------
__global__ void k_softmax() {
    int b = blockIdx.x;
    int tid = threadIdx.x;
    __shared__ float red[512];
    float sc = g_score[b * Ll + tid];
    red[tid] = sc;
    __syncthreads();
    for (int s = 256; s > 0; s >>= 1) {
        if (tid < s) red[tid] = fmaxf(red[tid], red[tid + s]);
        __syncthreads();
    }
    float m = red[0];
    __syncthreads();
    float e = expf(sc - m);
    red[tid] = e;
    __syncthreads();
    for (int s = 256; s > 0; s >>= 1) {
        if (tid < s) red[tid] += red[tid + s];
        __syncthreads();
    }
    g_prob[b * Ll + tid] = e / red[0];
}

// ---------------------------------------------------------------------------
// Kernel 4b: partial attention-weighted sum, grid(B,8), 64 positions each
// ---------------------------------------------------------------------------
__global__ void k_attn_part(const int* __restrict__ words,
                            const float* __restrict__ emb) {
    int b = blockIdx.x, ch = blockIdx.y;
    int tid = threadIdx.x;
    __shared__ float p[64];
    __shared__ int sw[64];
    int base = b * Ll + ch * 64;
    if (tid < 64) {
        p[tid] = g_prob[base + tid];
        sw[tid] = words[base + tid];
    }
    __syncthreads();
    if (tid < Dd) {
        float acc = 0.f;
        #pragma unroll 4
        for (int i = 0; i < 64; i++)
            acc += p[i] * emb[(long)sw[i] * Dd + tid];
        g_attn_part[(b * 8 + ch) * Dd + tid] = acc;
    }
}

// ---------------------------------------------------------------------------
// Kernel 5: feat = [attn, attn, subj, obj]; 2-layer relu MLP. grid = B
// ---------------------------------------------------------------------------
__global__ void k_mlp(const float* __restrict__ mw1, const float* __restrict__ mb1,
                      const float* __restrict__ mw2, const float* __restrict__ mb2,
                      float* __restrict__ out) {
    int b = blockIdx.x;
    int tid = threadIdx.x;
    __shared__ float feat[4 * Dd];
    __shared__ float hid[Hh];
    for (int i = tid; i < Dd; i += blockDim.x) {
        float a = 0.f;
        #pragma unroll
        for (int c = 0; c < 8; c++)
            a += g_attn_part[(b * 8 + c) * Dd + i];
        feat[i]          = a;            // subj_attn
        feat[Dd + i]     = a;            // obj_attn (== subj_attn, source bug)
        feat[2 * Dd + i] = g_subj[b * Dd + i];
        feat[3 * Dd + i] = g_obj[b * Dd + i];
    }
    __syncthreads();
    if (tid < Hh) {
        float a = mb1[tid];
        #pragma unroll 4
        for (int k = 0; k < 4 * Dd; k++)
            a += feat[k] * mw1[k * Hh + tid];
        hid[tid] = fmaxf(a, 0.f);
    }
    __syncthreads();
    if (tid < Hh) {
        float a = mb2[tid];
        #pragma unroll 4
        for (int k = 0; k < Hh; k++)
            a += hid[k] * mw2[k * Hh + tid];
        out[b * Hh + tid] = fmaxf(a, 0.f);
    }
}

// ---------------------------------------------------------------------------
extern "C" void kernel_launch(void* const* d_in, const int* in_sizes, int n_in,
                              void* d_out, int out_size) {
    const int*   words = (const int*)d_in[0];
    const int*   spos  = (const int*)d_in[1];
    const int*   opos  = (const int*)d_in[2];
    const float* emb   = (const float*)d_in[3];
    const float* w1    = (const float*)d_in[4];
    const float* b1    = (const float*)d_in[5];
    const float* w2    = (const float*)d_in[6];
    const float* b2    = (const float*)d_in[7];
    const float* mw1   = (const float*)d_in[8];
    const float* mb1   = (const float*)d_in[9];
    const float* mw2   = (const float*)d_in[10];
    const float* mb2   = (const float*)d_in[11];
    float* out = (float*)d_out;

    cudaFuncSetAttribute(k_fused, cudaFuncAttributeMaxDynamicSharedMemorySize,
                         FSM_TOTAL);

    k_prepW<<<70, 256>>>(w1);
    k_pools_part<<<dim3(Bb, 4), 320>>>(words, spos, opos, emb);
    k_pools_fin<<<Bb, 320>>>(w1, b1);
    k_fused<<<dim3(Bb, 4), 256, FSM_TOTAL>>>(words, emb, w2, b2);
    k_softmax<<<Bb, 512>>>();
    k_attn_part<<<dim3(Bb, 8), 320>>>(words, emb);
    k_mlp<<<Bb, 256>>>(mw1, mb1, mw2, mb2, out);
}

// round 7
// speedup vs baseline: 5.1682x; 1.5280x over previous
#include <cuda_runtime.h>
#include <cuda_fp16.h>
#include <math.h>
#include <stdint.h>

#define Bb 128
#define Ll 512
#define Dd 300
#define Hh 200
#define Vv 50000

#define KPAD 320        // Dd padded to 32
#define NPADW 224       // Hh padded to 224 (= 4 warps * 56)

// Scratch (device globals -- no allocation allowed)
__device__ __half g_Wh[NPADW * KPAD];        // fp16 W1_top^T, n-major, zero-padded
__device__ float  g_subj_part[Bb * 4 * Dd];
__device__ float  g_obj_part[Bb * 4 * Dd];
__device__ float  g_subj[Bb * Dd];
__device__ float  g_obj[Bb * Dd];
__device__ float  g_sup_part[Bb * 2 * Hh];   // sup-projection K partials
__device__ float  g_score[Bb * Ll];
__device__ float  g_prob[Bb * Ll];
__device__ float  g_attn_part[Bb * 8 * Dd];
__device__ float  g_hid_part[Bb * 4 * Hh];   // mlp layer-1 K partials

__device__ __forceinline__ void cp16(uint32_t dst, const void* src) {
    asm volatile("cp.async.cg.shared.global [%0], [%1], 16;\n"
                 :: "r"(dst), "l"(src));
}
__device__ __forceinline__ void cp16p(uint32_t dst, const void* src, bool v) {
    asm volatile("cp.async.cg.shared.global [%0], [%1], 16, %2;\n"
                 :: "r"(dst), "l"(src), "r"(v ? 16 : 0));
}
__device__ __forceinline__ uint32_t pkh2(float a, float b) {
    __half2 h = __floats2half2_rn(a, b);
    return *reinterpret_cast<uint32_t*>(&h);
}

// ---------------------------------------------------------------------------
// Kernel 0: W1_top f32 -> transposed padded f16 image g_Wh[n][k]
// ---------------------------------------------------------------------------
__global__ void k_prepW(const float* __restrict__ w1) {
    int idx = blockIdx.x * blockDim.x + threadIdx.x;
    int total = NPADW * KPAD;
    for (; idx < total; idx += gridDim.x * blockDim.x) {
        int n = idx / KPAD;
        int k = idx % KPAD;
        float v = (n < Hh && k < Dd) ? w1[k * Hh + n] : 0.f;
        g_Wh[idx] = __float2half(v);
    }
}

// ---------------------------------------------------------------------------
// Kernel 1a: partial masked max-pools, grid(B,4), 128 positions per block
// ---------------------------------------------------------------------------
__global__ void k_pools_part(const int* __restrict__ words,
                             const int* __restrict__ spos,
                             const int* __restrict__ opos,
                             const float* __restrict__ emb) {
    int b = blockIdx.x, ch = blockIdx.y;
    int tid = threadIdx.x;
    __shared__ int sl[128], ol[128];
    __shared__ int scnt, ocnt;
    if (tid == 0) { scnt = 0; ocnt = 0; }
    __syncthreads();
    int base = b * Ll + ch * 128;
    if (tid < 128) {
        int w = words[base + tid];
        if (spos[base + tid] == 0) sl[atomicAdd(&scnt, 1)] = w;
        if (opos[base + tid] == 0) ol[atomicAdd(&ocnt, 1)] = w;
    }
    __syncthreads();
    int ns = scnt, no = ocnt;
    if (tid < Dd) {
        float smax = -1e12f, omax = -1e12f;
        for (int i = 0; i < ns; i++)
            smax = fmaxf(smax, emb[(long)sl[i] * Dd + tid]);
        for (int i = 0; i < no; i++)
            omax = fmaxf(omax, emb[(long)ol[i] * Dd + tid]);
        g_subj_part[(b * 4 + ch) * Dd + tid] = smax;
        g_obj_part[(b * 4 + ch) * Dd + tid]  = omax;
    }
}

// ---------------------------------------------------------------------------
// Kernel 1b: combine partial maxes. grid = B, block = 320
// ---------------------------------------------------------------------------
__global__ void k_pools_fin() {
    int b = blockIdx.x;
    int tid = threadIdx.x;
    if (tid < Dd) {
        float s = -1e12f, o = -1e12f;
        #pragma unroll
        for (int c = 0; c < 4; c++) {
            s = fmaxf(s, g_subj_part[(b * 4 + c) * Dd + tid]);
            o = fmaxf(o, g_obj_part[(b * 4 + c) * Dd + tid]);
        }
        g_subj[b * Dd + tid] = s;
        g_obj[b * Dd + tid]  = o;
    }
}

// ---------------------------------------------------------------------------
// Kernel 1c: sup-projection K partials. grid (B, 2), block 256.
// g_sup_part[b,kc,h] = sum_{i<150} subj[b, kc*150+i] * w1[(300+kc*150+i), h]
// ---------------------------------------------------------------------------
__global__ void k_supproj(const float* __restrict__ w1) {
    int b = blockIdx.x, kc = blockIdx.y;
    int tid = threadIdx.x;
    __shared__ float ssub[152];
    if (tid < 150) ssub[tid] = g_subj[b * Dd + kc * 150 + tid];
    __syncthreads();
    if (tid < Hh) {
        float acc = 0.f;
        const float* wp = w1 + (Dd + kc * 150) * Hh + tid;
        #pragma unroll 10
        for (int i = 0; i < 150; i++)
            acc += ssub[i] * wp[i * Hh];
        g_sup_part[(b * 2 + kc) * Hh + tid] = acc;
    }
}

// ---------------------------------------------------------------------------
// Kernel 2 (FUSED): per 128-token tile, gather emb rows (fp32, cp.async,
// 3-stage pipeline, K chunks of 32), fp16 mma.sync m16n8k16 vs W1_top^T,
// then score[tok] = b2 + sum_n w2[n]*tanh(hid[tok,n]+sup[b,n]).
// grid (B, 4), 512 threads, 16 warps as 4(m) x 4(n), warp tile 32x56.
// ---------------------------------------------------------------------------
#define FSM_A    0              // float A[3][128][36] = 55296
#define FSM_B    55296          // half  B[3][224][40] = 53760
#define FSM_WD   109056         // int   wds[128]      = 512
#define FSM_SUP  109568         // float sup[224]      = 896
#define FSM_W2   110464         // float w2s[224]      = 896
#define FSM_SC   111360         // float sc[128]       = 512
#define FSM_TOTAL 111872

__global__ void __launch_bounds__(512) k_fused(const int* __restrict__ words,
                                               const float* __restrict__ emb,
                                               const float* __restrict__ w2,
                                               const float* __restrict__ b2,
                                               const float* __restrict__ b1) {
    extern __shared__ char sm[];
    uint32_t smBase;
    asm("{ .reg .u64 t; cvta.to.shared.u64 t, %1; cvt.u32.u64 %0, t; }"
        : "=r"(smBase) : "l"(sm));

    float* Af  = (float*)(sm + FSM_A);        // [3][128][36]
    __half* Bh = (__half*)(sm + FSM_B);       // [3][224][40]
    int*   wds = (int*)(sm + FSM_WD);
    float* sup = (float*)(sm + FSM_SUP);
    float* w2s = (float*)(sm + FSM_W2);
    float* sc  = (float*)(sm + FSM_SC);

    int b = blockIdx.x, ch = blockIdx.y;
    int tid = threadIdx.x;
    int wid = tid >> 5;
    int lane = tid & 31;
    int g = lane >> 2, t = lane & 3;
    int warp_m = wid >> 2;                    // 0..3
    int warp_n = wid & 3;                     // 0..3

    float bias = b2[0];
    if (tid < 128) {
        wds[tid] = words[b * Ll + ch * 128 + tid];
        sc[tid] = bias;
    }
    if (tid < NPADW) {
        if (tid < Hh) {
            sup[tid] = b1[tid] + g_sup_part[b * 2 * Hh + tid] +
                       g_sup_part[(b * 2 + 1) * Hh + tid];
            w2s[tid] = w2[tid];
        } else {
            sup[tid] = 0.f;
            w2s[tid] = 0.f;
        }
    }
    __syncthreads();

    int arow = tid >> 2;                      // 0..127
    int s0 = tid & 3;                         // segments s0, s0+4
    const float* rowsrc = emb + (long)wds[arow] * Dd;

    #define F_LOAD(buf, c)                                                    \
    {                                                                         \
        int kb = (c) * 32;                                                    \
        _Pragma("unroll")                                                     \
        for (int s = 0; s < 2; s++) {                                         \
            int seg = s0 + s * 4;                                             \
            bool v = (kb + seg * 4 + 4 <= Dd);                                \
            uint32_t dst = smBase + FSM_A +                                   \
                (uint32_t)((buf) * 4608 + arow * 36 + seg * 4) * 4u;          \
            cp16p(dst, rowsrc + kb + seg * 4, v);                             \
        }                                                                     \
        _Pragma("unroll")                                                     \
        for (int p = 0; p < 2; p++) {                                         \
            int idx = tid + p * 512;                                          \
            if (idx < 896) {                                                  \
                int r = idx >> 2, sg = idx & 3;                               \
                uint32_t dst = smBase + FSM_B +                               \
                    (uint32_t)((buf) * 8960 + r * 40 + sg * 8) * 2u;          \
                cp16(dst, g_Wh + r * KPAD + (c) * 32 + sg * 8);               \
            }                                                                 \
        }                                                                     \
        asm volatile("cp.async.commit_group;");                               \
    }

    float acc[2][7][4];
    #pragma unroll
    for (int i = 0; i < 2; i++)
        #pragma unroll
        for (int j = 0; j < 7; j++)
            #pragma unroll
            for (int c = 0; c < 4; c++) acc[i][j][c] = 0.f;

    F_LOAD(0, 0);
    F_LOAD(1, 1);

    const int NIT = KPAD / 32;                // 10
    for (int it = 0; it < NIT; it++) {
        asm volatile("cp.async.wait_group 1;");
        __syncthreads();
        {
            int nxt = it + 2;
            if (nxt < NIT) {
                int nb = nxt - (nxt / 3) * 3;
                F_LOAD(nb, nxt);
            }
        }
        int buf = it - (it / 3) * 3;
        const float* Afb = Af + buf * 4608;
        const __half* Bhb = Bh + buf * 8960;

        #pragma unroll
        for (int ks = 0; ks < 2; ks++) {
            int kl = ks * 16;
            uint32_t ua[2][4], ub[7][2];
            #pragma unroll
            for (int mt = 0; mt < 2; mt++) {
                int mr = warp_m * 32 + mt * 16;
                const float* r1 = Afb + (mr + g) * 36 + kl + 2 * t;
                const float* r2 = Afb + (mr + g + 8) * 36 + kl + 2 * t;
                ua[mt][0] = pkh2(r1[0], r1[1]);
                ua[mt][1] = pkh2(r2[0], r2[1]);
                ua[mt][2] = pkh2(r1[8], r1[9]);
                ua[mt][3] = pkh2(r2[8], r2[9]);
            }
            #pragma unroll
            for (int nt = 0; nt < 7; nt++) {
                int nc = warp_n * 56 + nt * 8;
                ub[nt][0] = *(const uint32_t*)&Bhb[(nc + g) * 40 + kl + 2 * t];
                ub[nt][1] = *(const uint32_t*)&Bhb[(nc + g) * 40 + kl + 2 * t + 8];
            }
            #pragma unroll
            for (int mt = 0; mt < 2; mt++)
                #pragma unroll
                for (int nt = 0; nt < 7; nt++)
                    asm volatile(
                        "mma.sync.aligned.m16n8k16.row.col.f32.f16.f16.f32 "
                        "{%0,%1,%2,%3}, {%4,%5,%6,%7}, {%8,%9}, {%0,%1,%2,%3};"
                        : "+f"(acc[mt][nt][0]), "+f"(acc[mt][nt][1]),
                          "+f"(acc[mt][nt][2]), "+f"(acc[mt][nt][3])
                        : "r"(ua[mt][0]), "r"(ua[mt][1]), "r"(ua[mt][2]), "r"(ua[mt][3]),
                          "r"(ub[nt][0]), "r"(ub[nt][1]));
        }
        __syncthreads();
    }

    // epilogue: score contributions
    #pragma unroll
    for (int mt = 0; mt < 2; mt++) {
        int r1 = warp_m * 32 + mt * 16 + g;
        float rs0 = 0.f, rs1 = 0.f;
        #pragma unroll
        for (int nt = 0; nt < 7; nt++) {
            int col = warp_n * 56 + nt * 8 + 2 * t;
            float wa = w2s[col], wb = w2s[col + 1];
            float sa = sup[col], sb = sup[col + 1];
            float t0, t1, t2, t3;
            asm("tanh.approx.f32 %0, %1;" : "=f"(t0) : "f"(acc[mt][nt][0] + sa));
            asm("tanh.approx.f32 %0, %1;" : "=f"(t1) : "f"(acc[mt][nt][1] + sb));
            asm("tanh.approx.f32 %0, %1;" : "=f"(t2) : "f"(acc[mt][nt][2] + sa));
            asm("tanh.approx.f32 %0, %1;" : "=f"(t3) : "f"(acc[mt][nt][3] + sb));
            rs0 += wa * t0 + wb * t1;
            rs1 += wa * t2 + wb * t3;
        }
        atomicAdd(&sc[r1], rs0);
        atomicAdd(&sc[r1 + 8], rs1);
    }
    __syncthreads();
    if (tid < 128)
        g_score[b * Ll + ch * 128 + tid] = sc[tid];
}

// ---------------------------------------------------------------------------
// Kernel 4a: per-b softmax -> normalized probs. grid = B, block = 512
// ---------------------------------------------------------------------------
__global__ void k_softmax() {
    int b = blockIdx.x;
    int tid = threadIdx.x;
    __shared__ float red[512];
    float sc = g_score[b * Ll + tid];
    red[tid] = sc;
    __syncthreads();
    for (int s = 256; s > 0; s >>= 1) {
        if (tid < s) red[tid] = fmaxf(red[tid], red[tid + s]);
        __syncthreads();
    }
    float m = red[0];
    __syncthreads();
    float e = expf(sc - m);
    red[tid] = e;
    __syncthreads();
    for (int s = 256; s > 0; s >>= 1) {
        if (tid < s) red[tid] += red[tid + s];
        __syncthreads();
    }
    g_prob[b * Ll + tid] = e / red[0];
}

// ---------------------------------------------------------------------------
// Kernel 4b: partial attention-weighted sum, grid(B,8), 64 positions each
// ---------------------------------------------------------------------------
__global__ void k_attn_part(const int* __restrict__ words,
                            const float* __restrict__ emb) {
    int b = blockIdx.x, ch = blockIdx.y;
    int tid = threadIdx.x;
    __shared__ float p[64];
    __shared__ int sw[64];
    int base = b * Ll + ch * 64;
    if (tid < 64) {
        p[tid] = g_prob[base + tid];
        sw[tid] = words[base + tid];
    }
    __syncthreads();
    if (tid < Dd) {
        float acc = 0.f;
        #pragma unroll 8
        for (int i = 0; i < 64; i++)
            acc += p[i] * emb[(long)sw[i] * Dd + tid];
        g_attn_part[(b * 8 + ch) * Dd + tid] = acc;
    }
}

// ---------------------------------------------------------------------------
// Kernel 5a: MLP layer-1 K partials. grid (B, 4), block 320.
// kc 0/1: v = attn (sum of 8 parts); kc 2: subj; kc 3: obj.
// part[b,kc,h] = sum_{i<300} v[i] * mw1[(kc*300+i), h]
// ---------------------------------------------------------------------------
__global__ void k_mlp1(const float* __restrict__ mw1) {
    int b = blockIdx.x, kc = blockIdx.y;
    int tid = threadIdx.x;
    __shared__ float v[Dd];
    if (tid < Dd) {
        float a;
        if (kc <= 1) {
            a = 0.f;
            #pragma unroll
            for (int c = 0; c < 8; c++)
                a += g_attn_part[(b * 8 + c) * Dd + tid];
        } else if (kc == 2) {
            a = g_subj[b * Dd + tid];
        } else {
            a = g_obj[b * Dd + tid];
        }
        v[tid] = a;
    }
    __syncthreads();
    if (tid < Hh) {
        float acc = 0.f;
        const float* wp = mw1 + kc * Dd * Hh + tid;
        #pragma unroll 10
        for (int i = 0; i < Dd; i++)
            acc += v[i] * wp[i * Hh];
        g_hid_part[(b * 4 + kc) * Hh + tid] = acc;
    }
}

// ---------------------------------------------------------------------------
// Kernel 5b: combine partials + relu, then layer 2. grid = B, block 256.
// ---------------------------------------------------------------------------
__global__ void k_mlp2(const float* __restrict__ mb1,
                       const float* __restrict__ mw2,
                       const float* __restrict__ mb2,
                       float* __restrict__ out) {
    int b = blockIdx.x;
    int tid = threadIdx.x;
    __shared__ float hid[Hh];
    if (tid < Hh) {
        float a = mb1[tid];
        #pragma unroll
        for (int c = 0; c < 4; c++)
            a += g_hid_part[(b * 4 + c) * Hh + tid];
        hid[tid] = fmaxf(a, 0.f);
    }
    __syncthreads();
    if (tid < Hh) {
        float a = mb2[tid];
        const float* wp = mw2 + tid;
        #pragma unroll 10
        for (int k = 0; k < Hh; k++)
            a += hid[k] * wp[k * Hh];
        out[b * Hh + tid] = fmaxf(a, 0.f);
    }
}

// ---------------------------------------------------------------------------
extern "C" void kernel_launch(void* const* d_in, const int* in_sizes, int n_in,
                              void* d_out, int out_size) {
    const int*   words = (const int*)d_in[0];
    const int*   spos  = (const int*)d_in[1];
    const int*   opos  = (const int*)d_in[2];
    const float* emb   = (const float*)d_in[3];
    const float* w1    = (const float*)d_in[4];
    const float* b1    = (const float*)d_in[5];
    const float* w2    = (const float*)d_in[6];
    const float* b2    = (const float*)d_in[7];
    const float* mw1   = (const float*)d_in[8];
    const float* mb1   = (const float*)d_in[9];
    const float* mw2   = (const float*)d_in[10];
    const float* mb2   = (const float*)d_in[11];
    float* out = (float*)d_out;

    cudaFuncSetAttribute(k_fused, cudaFuncAttributeMaxDynamicSharedMemorySize,
                         FSM_TOTAL);

    k_prepW<<<70, 256>>>(w1);
    k_pools_part<<<dim3(Bb, 4), 320>>>(words, spos, opos, emb);
    k_pools_fin<<<Bb, 320>>>();
    k_supproj<<<dim3(Bb, 2), 256>>>(w1);
    k_fused<<<dim3(Bb, 4), 512, FSM_TOTAL>>>(words, emb, w2, b2, b1);
    k_softmax<<<Bb, 512>>>();
    k_attn_part<<<dim3(Bb, 8), 320>>>(words, emb);
    k_mlp1<<<dim3(Bb, 4), 320>>>(mw1);
    k_mlp2<<<Bb, 256>>>(mb1, mw2, mb2, out);
}

// round 8
// speedup vs baseline: 5.5181x; 1.0677x over previous
#include <cuda_runtime.h>
#include <cuda_fp16.h>
#include <math.h>
#include <stdint.h>

#define Bb 128
#define Ll 512
#define Dd 300
#define Hh 200
#define Vv 50000

#define KPAD 320        // Dd padded to 32
#define NPADW 224       // Hh padded to 224 (= 4 warps * 56)

// Scratch (device globals -- no allocation allowed)
__device__ __half g_Wh[NPADW * KPAD];        // fp16 W1_top^T, n-major, zero-padded
__device__ float  g_subj_part[Bb * 8 * Dd];
__device__ float  g_obj_part[Bb * 8 * Dd];
__device__ float  g_subj[Bb * Dd];
__device__ float  g_obj[Bb * Dd];
__device__ float  g_sup_part[Bb * 6 * Hh];   // sup-projection K partials
__device__ float  g_score[Bb * Ll];
__device__ float  g_attn_part[Bb * 8 * Dd];
__device__ float  g_hid_part[Bb * 8 * Hh];   // mlp layer-1 K partials

__device__ __forceinline__ void cp16(uint32_t dst, const void* src) {
    asm volatile("cp.async.cg.shared.global [%0], [%1], 16;\n"
                 :: "r"(dst), "l"(src));
}
__device__ __forceinline__ void cp16p(uint32_t dst, const void* src, bool v) {
    asm volatile("cp.async.cg.shared.global [%0], [%1], 16, %2;\n"
                 :: "r"(dst), "l"(src), "r"(v ? 16 : 0));
}
__device__ __forceinline__ uint32_t pkh2(float a, float b) {
    __half2 h = __floats2half2_rn(a, b);
    return *reinterpret_cast<uint32_t*>(&h);
}

// ---------------------------------------------------------------------------
// Kernel 0: W1_top f32 -> transposed padded f16 image g_Wh[n][k]
// ---------------------------------------------------------------------------
__global__ void k_prepW(const float* __restrict__ w1) {
    int idx = blockIdx.x * blockDim.x + threadIdx.x;
    int total = NPADW * KPAD;
    for (; idx < total; idx += gridDim.x * blockDim.x) {
        int n = idx / KPAD;
        int k = idx % KPAD;
        float v = (n < Hh && k < Dd) ? w1[k * Hh + n] : 0.f;
        g_Wh[idx] = __float2half(v);
    }
}

// ---------------------------------------------------------------------------
// Kernel 1a: partial masked max-pools, grid(B,8), 64 positions per block
// ---------------------------------------------------------------------------
__global__ void k_pools_part(const int* __restrict__ words,
                             const int* __restrict__ spos,
                             const int* __restrict__ opos,
                             const float* __restrict__ emb) {
    int b = blockIdx.x, ch = blockIdx.y;
    int tid = threadIdx.x;
    __shared__ int sl[64], ol[64];
    __shared__ int scnt, ocnt;
    if (tid == 0) { scnt = 0; ocnt = 0; }
    __syncthreads();
    int base = b * Ll + ch * 64;
    if (tid < 64) {
        int w = words[base + tid];
        if (spos[base + tid] == 0) sl[atomicAdd(&scnt, 1)] = w;
        if (opos[base + tid] == 0) ol[atomicAdd(&ocnt, 1)] = w;
    }
    __syncthreads();
    int ns = scnt, no = ocnt;
    if (tid < Dd) {
        float smax = -1e12f, omax = -1e12f;
        for (int i = 0; i < ns; i++)
            smax = fmaxf(smax, emb[(long)sl[i] * Dd + tid]);
        for (int i = 0; i < no; i++)
            omax = fmaxf(omax, emb[(long)ol[i] * Dd + tid]);
        g_subj_part[(b * 8 + ch) * Dd + tid] = smax;
        g_obj_part[(b * 8 + ch) * Dd + tid]  = omax;
    }
}

// ---------------------------------------------------------------------------
// Kernel 1b: combine partial maxes. grid = B, block = 320
// ---------------------------------------------------------------------------
__global__ void k_pools_fin() {
    int b = blockIdx.x;
    int tid = threadIdx.x;
    if (tid < Dd) {
        float s = -1e12f, o = -1e12f;
        #pragma unroll
        for (int c = 0; c < 8; c++) {
            s = fmaxf(s, g_subj_part[(b * 8 + c) * Dd + tid]);
            o = fmaxf(o, g_obj_part[(b * 8 + c) * Dd + tid]);
        }
        g_subj[b * Dd + tid] = s;
        g_obj[b * Dd + tid]  = o;
    }
}

// ---------------------------------------------------------------------------
// Kernel 1c: sup-projection K partials. grid (B, 6), block 256.
// g_sup_part[b,kc,h] = sum_{i<50} subj[b, kc*50+i] * w1[(300+kc*50+i), h]
// ---------------------------------------------------------------------------
__global__ void k_supproj(const float* __restrict__ w1) {
    int b = blockIdx.x, kc = blockIdx.y;
    int tid = threadIdx.x;
    __shared__ float ssub[56];
    if (tid < 50) ssub[tid] = g_subj[b * Dd + kc * 50 + tid];
    __syncthreads();
    if (tid < Hh) {
        float acc = 0.f;
        const float* wp = w1 + (Dd + kc * 50) * Hh + tid;
        #pragma unroll 10
        for (int i = 0; i < 50; i++)
            acc += ssub[i] * wp[i * Hh];
        g_sup_part[(b * 6 + kc) * Hh + tid] = acc;
    }
}

// ---------------------------------------------------------------------------
// Kernel 2 (FUSED): per 128-token tile, gather emb rows (fp32, cp.async,
// 4-stage pipeline, single sync/chunk), fp16 mma.sync m16n8k16 vs W1_top^T,
// then score[tok] = b2 + sum_n w2[n]*tanh(hid[tok,n]+sup[b,n]).
// grid (B, 4), 512 threads, 16 warps as 4(m) x 4(n), warp tile 32x56.
// ---------------------------------------------------------------------------
#define FSM_A    0              // float A[4][128][36] = 73728
#define FSM_B    73728          // half  B[4][224][40] = 71680
#define FSM_WD   145408         // int   wds[128]      = 512
#define FSM_SUP  145920         // float sup[224]      = 896
#define FSM_W2   146816         // float w2s[224]      = 896
#define FSM_SC   147712         // float sc[128]       = 512
#define FSM_TOTAL 148224

__global__ void __launch_bounds__(512) k_fused(const int* __restrict__ words,
                                               const float* __restrict__ emb,
                                               const float* __restrict__ w2,
                                               const float* __restrict__ b2,
                                               const float* __restrict__ b1) {
    extern __shared__ char sm[];
    uint32_t smBase;
    asm("{ .reg .u64 t; cvta.to.shared.u64 t, %1; cvt.u32.u64 %0, t; }"
        : "=r"(smBase) : "l"(sm));

    float* Af  = (float*)(sm + FSM_A);        // [4][128][36]
    __half* Bh = (__half*)(sm + FSM_B);       // [4][224][40]
    int*   wds = (int*)(sm + FSM_WD);
    float* sup = (float*)(sm + FSM_SUP);
    float* w2s = (float*)(sm + FSM_W2);
    float* sc  = (float*)(sm + FSM_SC);

    int b = blockIdx.x, ch = blockIdx.y;
    int tid = threadIdx.x;
    int wid = tid >> 5;
    int lane = tid & 31;
    int g = lane >> 2, t = lane & 3;
    int warp_m = wid >> 2;                    // 0..3
    int warp_n = wid & 3;                     // 0..3

    float bias = b2[0];
    if (tid < 128) {
        wds[tid] = words[b * Ll + ch * 128 + tid];
        sc[tid] = bias;
    }
    if (tid < NPADW) {
        if (tid < Hh) {
            float s = b1[tid];
            #pragma unroll
            for (int c = 0; c < 6; c++)
                s += g_sup_part[(b * 6 + c) * Hh + tid];
            sup[tid] = s;
            w2s[tid] = w2[tid];
        } else {
            sup[tid] = 0.f;
            w2s[tid] = 0.f;
        }
    }
    __syncthreads();

    int arow = tid >> 2;                      // 0..127
    int s0 = tid & 3;                         // segments s0, s0+4
    const float* rowsrc = emb + (long)wds[arow] * Dd;

    #define F_LOAD(buf, c)                                                    \
    {                                                                         \
        int kb = (c) * 32;                                                    \
        _Pragma("unroll")                                                     \
        for (int s = 0; s < 2; s++) {                                         \
            int seg = s0 + s * 4;                                             \
            bool v = (kb + seg * 4 + 4 <= Dd);                                \
            uint32_t dst = smBase + FSM_A +                                   \
                (uint32_t)((buf) * 4608 + arow * 36 + seg * 4) * 4u;          \
            cp16p(dst, rowsrc + kb + seg * 4, v);                             \
        }                                                                     \
        _Pragma("unroll")                                                     \
        for (int p = 0; p < 2; p++) {                                         \
            int idx = tid + p * 512;                                          \
            if (idx < 896) {                                                  \
                int r = idx >> 2, sg = idx & 3;                               \
                uint32_t dst = smBase + FSM_B +                               \
                    (uint32_t)((buf) * 8960 + r * 40 + sg * 8) * 2u;          \
                cp16(dst, g_Wh + r * KPAD + (c) * 32 + sg * 8);               \
            }                                                                 \
        }                                                                     \
        asm volatile("cp.async.commit_group;");                               \
    }

    float acc[2][7][4];
    #pragma unroll
    for (int i = 0; i < 2; i++)
        #pragma unroll
        for (int j = 0; j < 7; j++)
            #pragma unroll
            for (int c = 0; c < 4; c++) acc[i][j][c] = 0.f;

    F_LOAD(0, 0);
    F_LOAD(1, 1);
    F_LOAD(2, 2);

    const int NIT = KPAD / 32;                // 10
    for (int it = 0; it < NIT; it++) {
        asm volatile("cp.async.wait_group 2;");
        __syncthreads();
        {
            int nxt = it + 3;
            if (nxt < NIT) F_LOAD(nxt & 3, nxt);
        }
        int buf = it & 3;
        const float* Afb = Af + buf * 4608;
        const __half* Bhb = Bh + buf * 8960;

        #pragma unroll
        for (int ks = 0; ks < 2; ks++) {
            int kl = ks * 16;
            uint32_t ua[2][4], ub[7][2];
            #pragma unroll
            for (int mt = 0; mt < 2; mt++) {
                int mr = warp_m * 32 + mt * 16;
                const float* r1 = Afb + (mr + g) * 36 + kl + 2 * t;
                const float* r2 = Afb + (mr + g + 8) * 36 + kl + 2 * t;
                ua[mt][0] = pkh2(r1[0], r1[1]);
                ua[mt][1] = pkh2(r2[0], r2[1]);
                ua[mt][2] = pkh2(r1[8], r1[9]);
                ua[mt][3] = pkh2(r2[8], r2[9]);
            }
            #pragma unroll
            for (int nt = 0; nt < 7; nt++) {
                int nc = warp_n * 56 + nt * 8;
                ub[nt][0] = *(const uint32_t*)&Bhb[(nc + g) * 40 + kl + 2 * t];
                ub[nt][1] = *(const uint32_t*)&Bhb[(nc + g) * 40 + kl + 2 * t + 8];
            }
            #pragma unroll
            for (int mt = 0; mt < 2; mt++)
                #pragma unroll
                for (int nt = 0; nt < 7; nt++)
                    asm volatile(
                        "mma.sync.aligned.m16n8k16.row.col.f32.f16.f16.f32 "
                        "{%0,%1,%2,%3}, {%4,%5,%6,%7}, {%8,%9}, {%0,%1,%2,%3};"
                        : "+f"(acc[mt][nt][0]), "+f"(acc[mt][nt][1]),
                          "+f"(acc[mt][nt][2]), "+f"(acc[mt][nt][3])
                        : "r"(ua[mt][0]), "r"(ua[mt][1]), "r"(ua[mt][2]), "r"(ua[mt][3]),
                          "r"(ub[nt][0]), "r"(ub[nt][1]));
        }
    }
    __syncthreads();

    // epilogue: score contributions; shfl-reduce over t (lanes g*4 + 0..3)
    #pragma unroll
    for (int mt = 0; mt < 2; mt++) {
        int r1 = warp_m * 32 + mt * 16 + g;
        float rs0 = 0.f, rs1 = 0.f;
        #pragma unroll
        for (int nt = 0; nt < 7; nt++) {
            int col = warp_n * 56 + nt * 8 + 2 * t;
            float wa = w2s[col], wb = w2s[col + 1];
            float sa = sup[col], sb = sup[col + 1];
            float t0, t1, t2, t3;
            asm("tanh.approx.f32 %0, %1;" : "=f"(t0) : "f"(acc[mt][nt][0] + sa));
            asm("tanh.approx.f32 %0, %1;" : "=f"(t1) : "f"(acc[mt][nt][1] + sb));
            asm("tanh.approx.f32 %0, %1;" : "=f"(t2) : "f"(acc[mt][nt][2] + sa));
            asm("tanh.approx.f32 %0, %1;" : "=f"(t3) : "f"(acc[mt][nt][3] + sb));
            rs0 += wa * t0 + wb * t1;
            rs1 += wa * t2 + wb * t3;
        }
        rs0 += __shfl_xor_sync(0xffffffffu, rs0, 1);
        rs0 += __shfl_xor_sync(0xffffffffu, rs0, 2);
        rs1 += __shfl_xor_sync(0xffffffffu, rs1, 1);
        rs1 += __shfl_xor_sync(0xffffffffu, rs1, 2);
        if (t == 0) {
            atomicAdd(&sc[r1], rs0);
            atomicAdd(&sc[r1 + 8], rs1);
        }
    }
    __syncthreads();
    if (tid < 128)
        g_score[b * Ll + ch * 128 + tid] = sc[tid];
}

// ---------------------------------------------------------------------------
// Kernel 4 (softmax fused): grid (B,8), block 512. Each block redoes the
// cheap 512-wide softmax reduction, then computes its 64-position partial
// attention-weighted sum.
// ---------------------------------------------------------------------------
__global__ void k_attn_part(const int* __restrict__ words,
                            const float* __restrict__ emb) {
    int b = blockIdx.x, ch = blockIdx.y;
    int tid = threadIdx.x;
    __shared__ float red[512];
    __shared__ float p[64];
    __shared__ int sw[64];
    float scv = g_score[b * Ll + tid];
    red[tid] = scv;
    __syncthreads();
    for (int s = 256; s > 0; s >>= 1) {
        if (tid < s) red[tid] = fmaxf(red[tid], red[tid + s]);
        __syncthreads();
    }
    float m = red[0];
    __syncthreads();
    red[tid] = expf(scv - m);
    __syncthreads();
    for (int s = 256; s > 0; s >>= 1) {
        if (tid < s) red[tid] += red[tid + s];
        __syncthreads();
    }
    float inv = 1.f / red[0];
    int base = b * Ll + ch * 64;
    if (tid < 64) {
        p[tid] = expf(g_score[base + tid] - m) * inv;
        sw[tid] = words[base + tid];
    }
    __syncthreads();
    if (tid < Dd) {
        float acc = 0.f;
        #pragma unroll 8
        for (int i = 0; i < 64; i++)
            acc += p[i] * emb[(long)sw[i] * Dd + tid];
        g_attn_part[(b * 8 + ch) * Dd + tid] = acc;
    }
}

// ---------------------------------------------------------------------------
// Kernel 5a: MLP layer-1 K partials. grid (B, 8), block 256, chunks of 150.
// feat segment seg = kc/2 (0/1: attn; 2: subj; 3: obj), half = kc&1.
// ---------------------------------------------------------------------------
__global__ void k_mlp1(const float* __restrict__ mw1) {
    int b = blockIdx.x, kc = blockIdx.y;
    int seg = kc >> 1, half = kc & 1;
    int tid = threadIdx.x;
    __shared__ float v[152];
    if (tid < 150) {
        int i = half * 150 + tid;
        float a;
        if (seg <= 1) {
            a = 0.f;
            #pragma unroll
            for (int c = 0; c < 8; c++)
                a += g_attn_part[(b * 8 + c) * Dd + i];
        } else if (seg == 2) {
            a = g_subj[b * Dd + i];
        } else {
            a = g_obj[b * Dd + i];
        }
        v[tid] = a;
    }
    __syncthreads();
    if (tid < Hh) {
        float acc = 0.f;
        const float* wp = mw1 + (seg * Dd + half * 150) * Hh + tid;
        #pragma unroll 10
        for (int i = 0; i < 150; i++)
            acc += v[i] * wp[i * Hh];
        g_hid_part[(b * 8 + kc) * Hh + tid] = acc;
    }
}

// ---------------------------------------------------------------------------
// Kernel 5b: combine partials + relu, then layer 2. grid = B, block 256.
// ---------------------------------------------------------------------------
__global__ void k_mlp2(const float* __restrict__ mb1,
                       const float* __restrict__ mw2,
                       const float* __restrict__ mb2,
                       float* __restrict__ out) {
    int b = blockIdx.x;
    int tid = threadIdx.x;
    __shared__ float hid[Hh];
    if (tid < Hh) {
        float a = mb1[tid];
        #pragma unroll
        for (int c = 0; c < 8; c++)
            a += g_hid_part[(b * 8 + c) * Hh + tid];
        hid[tid] = fmaxf(a, 0.f);
    }
    __syncthreads();
    if (tid < Hh) {
        float a = mb2[tid];
        const float* wp = mw2 + tid;
        #pragma unroll 10
        for (int k = 0; k < Hh; k++)
            a += hid[k] * wp[k * Hh];
        out[b * Hh + tid] = fmaxf(a, 0.f);
    }
}

// ---------------------------------------------------------------------------
extern "C" void kernel_launch(void* const* d_in, const int* in_sizes, int n_in,
                              void* d_out, int out_size) {
    const int*   words = (const int*)d_in[0];
    const int*   spos  = (const int*)d_in[1];
    const int*   opos  = (const int*)d_in[2];
    const float* emb   = (const float*)d_in[3];
    const float* w1    = (const float*)d_in[4];
    const float* b1    = (const float*)d_in[5];
    const float* w2    = (const float*)d_in[6];
    const float* b2    = (const float*)d_in[7];
    const float* mw1   = (const float*)d_in[8];
    const float* mb1   = (const float*)d_in[9];
    const float* mw2   = (const float*)d_in[10];
    const float* mb2   = (const float*)d_in[11];
    float* out = (float*)d_out;

    cudaFuncSetAttribute(k_fused, cudaFuncAttributeMaxDynamicSharedMemorySize,
                         FSM_TOTAL);

    k_prepW<<<70, 256>>>(w1);
    k_pools_part<<<dim3(Bb, 8), 320>>>(words, spos, opos, emb);
    k_pools_fin<<<Bb, 320>>>();
    k_supproj<<<dim3(Bb, 6), 256>>>(w1);
    k_fused<<<dim3(Bb, 4), 512, FSM_TOTAL>>>(words, emb, w2, b2, b1);
    k_attn_part<<<dim3(Bb, 8), 512>>>(words, emb);
    k_mlp1<<<dim3(Bb, 8), 256>>>(mw1);
    k_mlp2<<<Bb, 256>>>(mb1, mw2, mb2, out);
}